// round 1
// baseline (speedup 1.0000x reference)
#include <cuda_runtime.h>
#include <cuda_bf16.h>
#include <cstdint>

// Problem constants
#define BB 32
#define NN 1024
#define VV 512
#define DD 1536
#define SP 132  // padded smem row (multiple of 4 for float4 alignment)

// Scratch buffers (allocation-free rule: __device__ globals)
__device__ float g_S [(size_t)BB*NN*NN];
__device__ float g_P [(size_t)BB*NN*NN];
__device__ float g_T [(size_t)BB*NN*NN];
__device__ float g_A [(size_t)BB*NN*NN];
__device__ float g_PN[(size_t)BB*NN*NN];
__device__ float g_q [BB*DD];
__device__ float g_u [BB*NN];
__device__ float g_sr[BB*NN];
__device__ float g_a [BB*NN];
__device__ float g_p [BB*NN];
__device__ float g_c [BB*VV];

// ---------------------------------------------------------------------------
// S_k[m,m'] = R[t_m,t_m'] + R[t_m,V+m'] + R[V+m,t_m'] + R[V+m,V+m']
//           = W[m, t_m'] + W[m, V+m'],  W[m,:] = R[t_m,:] + R[V+m,:]
// One block per (m, b): build W row in smem, gather columns.
// ---------------------------------------------------------------------------
__global__ void gather_S(const float* __restrict__ R, const int* __restrict__ tok,
                         float* __restrict__ S) {
    int b = blockIdx.y, m = blockIdx.x;
    __shared__ float Wsh[DD];
    __shared__ int   tsh[NN];
    const int* tb = tok + b*NN;
    int tm = tb[m];
    for (int d = threadIdx.x; d < DD; d += blockDim.x)
        Wsh[d] = R[(size_t)tm*DD + d] + R[(size_t)(VV + m)*DD + d];
    for (int i = threadIdx.x; i < NN; i += blockDim.x) tsh[i] = tb[i];
    __syncthreads();
    float* Srow = S + ((size_t)b*NN + m)*NN;
    for (int mp = threadIdx.x; mp < NN; mp += blockDim.x)
        Srow[mp] = Wsh[tsh[mp]] + Wsh[VV + mp];
}

// ---------------------------------------------------------------------------
// Causal row softmax: A[n,m] = softmax over m<=n of S[n,m]; zeros for m>n.
// In-place safe (same-thread same-index read->write).
// ---------------------------------------------------------------------------
__global__ void softmax_causal(const float* __restrict__ S, float* __restrict__ A) {
    int b = blockIdx.y, n = blockIdx.x;
    const float* srow = S + ((size_t)b*NN + n)*NN;
    float*       arow = A + ((size_t)b*NN + n)*NN;
    int len = n + 1;
    __shared__ float red[256];
    float mx = -1e30f;
    for (int m = threadIdx.x; m < len; m += 256) mx = fmaxf(mx, srow[m]);
    red[threadIdx.x] = mx; __syncthreads();
    for (int s = 128; s > 0; s >>= 1) {
        if (threadIdx.x < s) red[threadIdx.x] = fmaxf(red[threadIdx.x], red[threadIdx.x+s]);
        __syncthreads();
    }
    mx = red[0]; __syncthreads();
    float sum = 0.f;
    for (int m = threadIdx.x; m < len; m += 256) {
        float e = __expf(srow[m] - mx);
        arow[m] = e; sum += e;
    }
    red[threadIdx.x] = sum; __syncthreads();
    for (int s = 128; s > 0; s >>= 1) {
        if (threadIdx.x < s) red[threadIdx.x] += red[threadIdx.x+s];
        __syncthreads();
    }
    float inv = 1.f / red[0];
    for (int m = threadIdx.x; m < len; m += 256) arow[m] *= inv;
    for (int m = len + threadIdx.x; m < NN; m += 256) arow[m] = 0.f;
}

// ---------------------------------------------------------------------------
// Batched 1024x1024x1024 fp32 GEMM, 128x128x16 tiles, 256 threads, 8x8/thread.
// MODE 0: C = A*B          (A lower-tri: k in [0, (bi+1)*128))          all tiles
// MODE 1: C = A*B^T        (B lower-tri: k in [0, (bj+1)*128))          tiles j<=i
// MODE 2: C = A*B          (both lower:  k in [bj*128, (bi+1)*128))     tiles j<=i,
//                           epilogue zeroes strict-upper entries.
// ---------------------------------------------------------------------------
template<int MODE>
__global__ void __launch_bounds__(256)
gemm128(const float* __restrict__ Ag, const float* __restrict__ Bg,
        float* __restrict__ Cg) {
    int bi = blockIdx.y, bj = blockIdx.x, b = blockIdx.z;
    if (MODE != 0 && bj > bi) return;
    const float* Ab = Ag + (size_t)b*NN*NN;
    const float* Bb = Bg + (size_t)b*NN*NN;
    float*       Cb = Cg + (size_t)b*NN*NN;
    int k0 = (MODE == 2) ? bj*128 : 0;
    int k1 = (MODE == 1) ? (bj+1)*128 : (bi+1)*128;
    __shared__ float As[16][SP];
    __shared__ float Bs[16][SP];
    float acc[8][8] = {};
    int tid = threadIdx.x;
    int tx = tid & 15, ty = tid >> 4;
    int row0 = bi*128, col0 = bj*128;
    for (int kb = k0; kb < k1; kb += 16) {
        {   // load A tile 128x16, transpose into As[k][m]
            int r  = tid >> 2;
            int c4 = (tid & 3) * 4;
            #pragma unroll
            for (int h = 0; h < 2; h++) {
                float4 v = *(const float4*)&Ab[(size_t)(row0 + r + h*64)*NN + kb + c4];
                As[c4+0][r+h*64] = v.x; As[c4+1][r+h*64] = v.y;
                As[c4+2][r+h*64] = v.z; As[c4+3][r+h*64] = v.w;
            }
        }
        if (MODE == 1) {  // B^T: Bs[k][n] = Bphys[col0+n][k]
            int r  = tid >> 2;
            int c4 = (tid & 3) * 4;
            #pragma unroll
            for (int h = 0; h < 2; h++) {
                float4 v = *(const float4*)&Bb[(size_t)(col0 + r + h*64)*NN + kb + c4];
                Bs[c4+0][r+h*64] = v.x; Bs[c4+1][r+h*64] = v.y;
                Bs[c4+2][r+h*64] = v.z; Bs[c4+3][r+h*64] = v.w;
            }
        } else {          // B normal: Bs[k][n] = Bphys[kb+k][col0+n]
            int kr = tid >> 5;
            int n4 = (tid & 31) * 4;
            #pragma unroll
            for (int h = 0; h < 2; h++)
                *(float4*)&Bs[kr + h*8][n4] =
                    *(const float4*)&Bb[(size_t)(kb + kr + h*8)*NN + col0 + n4];
        }
        __syncthreads();
        #pragma unroll
        for (int kk = 0; kk < 16; kk++) {
            float a[8], w[8];
            *(float4*)&a[0] = *(const float4*)&As[kk][ty*8];
            *(float4*)&a[4] = *(const float4*)&As[kk][ty*8+4];
            *(float4*)&w[0] = *(const float4*)&Bs[kk][tx*8];
            *(float4*)&w[4] = *(const float4*)&Bs[kk][tx*8+4];
            #pragma unroll
            for (int i = 0; i < 8; i++)
                #pragma unroll
                for (int j = 0; j < 8; j++)
                    acc[i][j] += a[i] * w[j];
        }
        __syncthreads();
    }
    #pragma unroll
    for (int i = 0; i < 8; i++) {
        int gr = row0 + ty*8 + i;
        #pragma unroll
        for (int j = 0; j < 8; j += 4) {
            int gc = col0 + tx*8 + j;
            float4 v = make_float4(acc[i][j], acc[i][j+1], acc[i][j+2], acc[i][j+3]);
            if (MODE == 2) {  // enforce exact lower-triangularity
                if (gc+0 > gr) v.x = 0.f;
                if (gc+1 > gr) v.y = 0.f;
                if (gc+2 > gr) v.z = 0.f;
                if (gc+3 > gr) v.w = 0.f;
            }
            *(float4*)&Cb[(size_t)gr*NN + gc] = v;
        }
    }
}

// ---------------------------------------------------------------------------
// Layer 4 collapses to row 1023 only:
//   q = P[1023,:] @ W4 (weighted sum of gathered R4 rows)
//   u[m'] = q[t_m'] + q[V+m']          (= P[1023,:] @ S4)
//   srow  = P @ u                      (scores row 1023, pre-Pt)  [note: P S4 Pt row]
//   a = softmax(srow) ; p = a @ P ;  logits[v] = sum_m p[m]*(U[v,t_m]+U[v,V+m])
// ---------------------------------------------------------------------------
__global__ void l4_q(const float* __restrict__ R, const int* __restrict__ tok,
                     const float* __restrict__ P, float* __restrict__ q) {
    int b = blockIdx.x;
    __shared__ float rsh[NN];
    __shared__ int   tsh[NN];
    for (int i = threadIdx.x; i < NN; i += blockDim.x) {
        rsh[i] = P[((size_t)b*NN + (NN-1))*NN + i];
        tsh[i] = tok[b*NN + i];
    }
    __syncthreads();
    int d0 = threadIdx.x, d1 = d0 + 512, d2 = d0 + 1024;
    float a0 = 0.f, a1 = 0.f, a2 = 0.f;
    for (int m = 0; m < NN; m++) {
        float r = rsh[m];
        const float* Rt = R + (size_t)tsh[m]*DD;
        const float* Rp = R + (size_t)(VV + m)*DD;
        a0 += r * (Rt[d0] + Rp[d0]);
        a1 += r * (Rt[d1] + Rp[d1]);
        a2 += r * (Rt[d2] + Rp[d2]);
    }
    q[b*DD + d0] = a0; q[b*DD + d1] = a1; q[b*DD + d2] = a2;
}

__global__ void l4_u(const float* __restrict__ q, const int* __restrict__ tok,
                     float* __restrict__ u) {
    int b = blockIdx.x;
    for (int m = threadIdx.x; m < NN; m += blockDim.x) {
        int t = tok[b*NN + m];
        u[b*NN + m] = q[b*DD + t] + q[b*DD + VV + m];
    }
}

__global__ void l4_srow(const float* __restrict__ u, const float* __restrict__ P,
                        float* __restrict__ srow) {
    int b = blockIdx.y;
    __shared__ float ush[NN];
    for (int i = threadIdx.x; i < NN; i += 256) ush[i] = u[b*NN + i];
    __syncthreads();
    int row  = blockIdx.x * 8 + (threadIdx.x >> 5);
    int lane = threadIdx.x & 31;
    const float* Prow = P + ((size_t)b*NN + row)*NN;
    float acc = 0.f;
    for (int k = lane; k < NN; k += 32) acc += ush[k] * Prow[k];
    for (int o = 16; o; o >>= 1) acc += __shfl_down_sync(0xffffffffu, acc, o);
    if (lane == 0) srow[b*NN + row] = acc;
}

__global__ void l4_softmax(const float* __restrict__ s, float* __restrict__ a) {
    int b = blockIdx.x;
    __shared__ float red[256];
    float mx = -1e30f;
    for (int m = threadIdx.x; m < NN; m += 256) mx = fmaxf(mx, s[b*NN + m]);
    red[threadIdx.x] = mx; __syncthreads();
    for (int st = 128; st > 0; st >>= 1) {
        if (threadIdx.x < st) red[threadIdx.x] = fmaxf(red[threadIdx.x], red[threadIdx.x+st]);
        __syncthreads();
    }
    mx = red[0]; __syncthreads();
    float sum = 0.f;
    for (int m = threadIdx.x; m < NN; m += 256) {
        float e = __expf(s[b*NN + m] - mx);
        a[b*NN + m] = e; sum += e;
    }
    red[threadIdx.x] = sum; __syncthreads();
    for (int st = 128; st > 0; st >>= 1) {
        if (threadIdx.x < st) red[threadIdx.x] += red[threadIdx.x+st];
        __syncthreads();
    }
    float inv = 1.f / red[0];
    for (int m = threadIdx.x; m < NN; m += 256) a[b*NN + m] *= inv;
}

__global__ void l4_p(const float* __restrict__ a, const float* __restrict__ P,
                     float* __restrict__ p) {
    int b = blockIdx.y;
    int k = blockIdx.x * 256 + threadIdx.x;
    __shared__ float ash[NN];
    for (int i = threadIdx.x; i < NN; i += 256) ash[i] = a[b*NN + i];
    __syncthreads();
    float acc = 0.f;
    for (int m = 0; m < NN; m++) acc += ash[m] * P[((size_t)b*NN + m)*NN + k];
    p[b*NN + k] = acc;
}

// Deterministic scatter-free token accumulation: c[w] = sum_{m: t_m==w} p[m]
__global__ void l4_c(const int* __restrict__ tok, const float* __restrict__ p,
                     float* __restrict__ c) {
    int b = blockIdx.x;
    __shared__ float psh[NN];
    __shared__ int   tsh[NN];
    for (int i = threadIdx.x; i < NN; i += blockDim.x) {
        psh[i] = p[b*NN + i];
        tsh[i] = tok[b*NN + i];
    }
    __syncthreads();
    int w = threadIdx.x;  // blockDim.x == 512 == VV
    float acc = 0.f;
    for (int m = 0; m < NN; m++)
        if (tsh[m] == w) acc += psh[m];
    c[b*VV + w] = acc;
}

__global__ void l4_logits(const float* __restrict__ c, const float* __restrict__ p,
                          const float* __restrict__ U, float* __restrict__ out) {
    int b = blockIdx.y;
    __shared__ float hsh[DD];
    for (int i = threadIdx.x; i < VV; i += 256) hsh[i]      = c[b*VV + i];
    for (int i = threadIdx.x; i < NN; i += 256) hsh[VV + i] = p[b*NN + i];
    __syncthreads();
    int wid = threadIdx.x >> 5, lane = threadIdx.x & 31;
    int v = blockIdx.x * 8 + wid;
    const float* Ur = U + (size_t)v*DD;
    float acc = 0.f;
    for (int j = lane; j < DD; j += 32) acc += hsh[j] * Ur[j];
    for (int o = 16; o; o >>= 1) acc += __shfl_down_sync(0xffffffffu, acc, o);
    if (lane == 0) out[b*VV + v] = acc;
}

// ---------------------------------------------------------------------------
extern "C" void kernel_launch(void* const* d_in, const int* in_sizes, int n_in,
                              void* d_out, int out_size) {
    const int*   tok = (const int*)  d_in[0];
    const float* R   = (const float*)d_in[1];
    const float* U   = (const float*)d_in[2];
    float*       out = (float*)d_out;

    float *S, *P, *T, *A, *PN, *q, *u, *sr, *a, *p, *c;
    cudaGetSymbolAddress((void**)&S,  g_S);
    cudaGetSymbolAddress((void**)&P,  g_P);
    cudaGetSymbolAddress((void**)&T,  g_T);
    cudaGetSymbolAddress((void**)&A,  g_A);
    cudaGetSymbolAddress((void**)&PN, g_PN);
    cudaGetSymbolAddress((void**)&q,  g_q);
    cudaGetSymbolAddress((void**)&u,  g_u);
    cudaGetSymbolAddress((void**)&sr, g_sr);
    cudaGetSymbolAddress((void**)&a,  g_a);
    cudaGetSymbolAddress((void**)&p,  g_p);
    cudaGetSymbolAddress((void**)&c,  g_c);

    dim3 gRow(NN, BB), gT(8, 8, BB);
    const size_t RS = (size_t)DD*DD;

    // Layer 1: P2 = A1 = softmax(S1)  (P1 = I, so scores == S1)
    gather_S      <<<gRow, 256>>>(R + 0*RS, tok, S);
    softmax_causal<<<gRow, 256>>>(S, P);

    // Layer 2: scores = P*S2*P^T ; A2 = softmax ; P3 = A2*P
    gather_S      <<<gRow, 256>>>(R + 1*RS, tok, S);
    gemm128<0>    <<<gT, 256>>>(P, S, T);
    gemm128<1>    <<<gT, 256>>>(T, P, A);
    softmax_causal<<<gRow, 256>>>(A, A);
    gemm128<2>    <<<gT, 256>>>(A, P, PN);

    // Layer 3: same with P3 (in PN) -> P4 (into P)
    gather_S      <<<gRow, 256>>>(R + 2*RS, tok, S);
    gemm128<0>    <<<gT, 256>>>(PN, S, T);
    gemm128<1>    <<<gT, 256>>>(T, PN, A);
    softmax_causal<<<gRow, 256>>>(A, A);
    gemm128<2>    <<<gT, 256>>>(A, PN, P);

    // Layer 4 (row 1023 only) + logits
    l4_q      <<<BB, 512>>>(R + 3*RS, tok, P, q);
    l4_u      <<<BB, 256>>>(q, tok, u);
    l4_srow   <<<dim3(128, BB), 256>>>(u, P, sr);
    l4_softmax<<<BB, 256>>>(sr, a);
    l4_p      <<<dim3(4, BB), 256>>>(a, P, p);
    l4_c      <<<BB, 512>>>(tok, p, c);
    l4_logits <<<dim3(64, BB), 256>>>(c, p, U, out);
}

// round 3
// speedup vs baseline: 1.6482x; 1.6482x over previous
#include <cuda_runtime.h>
#include <cuda_bf16.h>
#include <cstdint>

// Problem constants
#define BB 32
#define NN 1024
#define VV 512
#define DD 1536
#define SP 132  // padded smem row

// Scratch buffers (allocation-free rule: __device__ globals)
__device__ float g_S [(size_t)BB*NN*NN];
__device__ float g_P [(size_t)BB*NN*NN];
__device__ float g_T [(size_t)BB*NN*NN];
__device__ float g_A [(size_t)BB*NN*NN];
__device__ float g_PN[(size_t)BB*NN*NN];
__device__ float g_q [BB*DD];
__device__ float g_u [BB*NN];
__device__ float g_sr[BB*NN];
__device__ float g_a [BB*NN];
__device__ float g_p [BB*NN];
__device__ float g_c [BB*VV];

// cvt.rna.tf32.f32 requires a .b32 destination register.
__device__ __forceinline__ float to_tf32(float x) {
    uint32_t u;
    asm("cvt.rna.tf32.f32 %0, %1;" : "=r"(u) : "f"(x));
    return __uint_as_float(u);
}

// ---------------------------------------------------------------------------
// S_k[m,m'] = W[m, t_m'] + W[m, V+m'],  W[m,:] = R[t_m,:] + R[V+m,:]
// ---------------------------------------------------------------------------
__global__ void gather_S(const float* __restrict__ R, const int* __restrict__ tok,
                         float* __restrict__ S) {
    int b = blockIdx.y, m = blockIdx.x;
    __shared__ float Wsh[DD];
    __shared__ int   tsh[NN];
    const int* tb = tok + b*NN;
    int tm = tb[m];
    for (int d = threadIdx.x; d < DD; d += blockDim.x)
        Wsh[d] = R[(size_t)tm*DD + d] + R[(size_t)(VV + m)*DD + d];
    for (int i = threadIdx.x; i < NN; i += blockDim.x) tsh[i] = tb[i];
    __syncthreads();
    float* Srow = S + ((size_t)b*NN + m)*NN;
    for (int mp = threadIdx.x; mp < NN; mp += blockDim.x)
        Srow[mp] = Wsh[tsh[mp]] + Wsh[VV + mp];
}

// ---------------------------------------------------------------------------
// Causal row softmax (in-place safe)
// ---------------------------------------------------------------------------
__global__ void softmax_causal(const float* __restrict__ S, float* __restrict__ A) {
    int b = blockIdx.y, n = blockIdx.x;
    const float* srow = S + ((size_t)b*NN + n)*NN;
    float*       arow = A + ((size_t)b*NN + n)*NN;
    int len = n + 1;
    __shared__ float red[256];
    float mx = -1e30f;
    for (int m = threadIdx.x; m < len; m += 256) mx = fmaxf(mx, srow[m]);
    red[threadIdx.x] = mx; __syncthreads();
    for (int s = 128; s > 0; s >>= 1) {
        if (threadIdx.x < s) red[threadIdx.x] = fmaxf(red[threadIdx.x], red[threadIdx.x+s]);
        __syncthreads();
    }
    mx = red[0]; __syncthreads();
    float sum = 0.f;
    for (int m = threadIdx.x; m < len; m += 256) {
        float e = __expf(srow[m] - mx);
        arow[m] = e; sum += e;
    }
    red[threadIdx.x] = sum; __syncthreads();
    for (int s = 128; s > 0; s >>= 1) {
        if (threadIdx.x < s) red[threadIdx.x] += red[threadIdx.x+s];
        __syncthreads();
    }
    float inv = 1.f / red[0];
    for (int m = threadIdx.x; m < len; m += 256) arow[m] *= inv;
    for (int m = len + threadIdx.x; m < NN; m += 256) arow[m] = 0.f;
}

// ---------------------------------------------------------------------------
// Batched 1024^3 GEMM on tensor cores: tf32 mma.sync m16n8k8, fp32 accum.
// 128x128 block tile, 8 warps as 4(m) x 2(n), warp tile 32x64.
// MODE 0: C = A*B          k in [0, (bi+1)*128)            all tiles
// MODE 1: C = A*B^T        k in [0, (bj+1)*128)            tiles j<=i
// MODE 2: C = A*B          k in [bj*128, (bi+1)*128)       tiles j<=i, zero upper
// ---------------------------------------------------------------------------
template<int MODE>
__global__ void __launch_bounds__(256)
gemm_tf32(const float* __restrict__ Ag, const float* __restrict__ Bg,
          float* __restrict__ Cg) {
    int bi = blockIdx.y, bj = blockIdx.x, b = blockIdx.z;
    if (MODE != 0 && bj > bi) return;
    const float* Ab = Ag + (size_t)b*NN*NN;
    const float* Bb = Bg + (size_t)b*NN*NN;
    float*       Cb = Cg + (size_t)b*NN*NN;
    int k0 = (MODE == 2) ? bj*128 : 0;
    int k1 = (MODE == 1) ? (bj+1)*128 : (bi+1)*128;

    __shared__ float As[16][SP];   // k-major: As[k][m]
    __shared__ float Bs[16][SP];   // k-major: Bs[k][n]

    int tid  = threadIdx.x;
    int wid  = tid >> 5, lane = tid & 31;
    int gid  = lane >> 2, tig = lane & 3;
    int wm   = (wid & 3) * 32;     // warp m-offset in tile
    int wn   = (wid >> 2) * 64;    // warp n-offset in tile
    int row0 = bi*128, col0 = bj*128;

    float c[2][8][4];
    #pragma unroll
    for (int i = 0; i < 2; i++)
        #pragma unroll
        for (int j = 0; j < 8; j++)
            #pragma unroll
            for (int r = 0; r < 4; r++) c[i][j][r] = 0.f;

    for (int kb = k0; kb < k1; kb += 16) {
        {   // A tile 128x16 -> As[k][m] (transposed), converted to tf32
            int r  = tid >> 2;
            int c4 = (tid & 3) * 4;
            #pragma unroll
            for (int h = 0; h < 2; h++) {
                float4 v = *(const float4*)&Ab[(size_t)(row0 + r + h*64)*NN + kb + c4];
                As[c4+0][r+h*64] = to_tf32(v.x); As[c4+1][r+h*64] = to_tf32(v.y);
                As[c4+2][r+h*64] = to_tf32(v.z); As[c4+3][r+h*64] = to_tf32(v.w);
            }
        }
        if (MODE == 1) {  // B^T: Bs[k][n] = Bphys[col0+n][k]
            int r  = tid >> 2;
            int c4 = (tid & 3) * 4;
            #pragma unroll
            for (int h = 0; h < 2; h++) {
                float4 v = *(const float4*)&Bb[(size_t)(col0 + r + h*64)*NN + kb + c4];
                Bs[c4+0][r+h*64] = to_tf32(v.x); Bs[c4+1][r+h*64] = to_tf32(v.y);
                Bs[c4+2][r+h*64] = to_tf32(v.z); Bs[c4+3][r+h*64] = to_tf32(v.w);
            }
        } else {          // B normal: Bs[k][n] = Bphys[kb+k][col0+n]
            int kr = tid >> 5;
            int n4 = (tid & 31) * 4;
            #pragma unroll
            for (int h = 0; h < 2; h++) {
                float4 v = *(const float4*)&Bb[(size_t)(kb + kr + h*8)*NN + col0 + n4];
                Bs[kr+h*8][n4+0] = to_tf32(v.x); Bs[kr+h*8][n4+1] = to_tf32(v.y);
                Bs[kr+h*8][n4+2] = to_tf32(v.z); Bs[kr+h*8][n4+3] = to_tf32(v.w);
            }
        }
        __syncthreads();

        #pragma unroll
        for (int kk = 0; kk < 16; kk += 8) {
            // A fragments: m16k8 per frag, 2 frags cover warp's 32 rows
            uint32_t a[2][4];
            #pragma unroll
            for (int i = 0; i < 2; i++) {
                int m0 = wm + i*16;
                a[i][0] = __float_as_uint(As[kk+tig  ][m0+gid  ]);
                a[i][1] = __float_as_uint(As[kk+tig  ][m0+gid+8]);
                a[i][2] = __float_as_uint(As[kk+tig+4][m0+gid  ]);
                a[i][3] = __float_as_uint(As[kk+tig+4][m0+gid+8]);
            }
            // B fragments: k8n8, 8 frags cover warp's 64 cols
            uint32_t bfr[8][2];
            #pragma unroll
            for (int j = 0; j < 8; j++) {
                int n0 = wn + j*8;
                bfr[j][0] = __float_as_uint(Bs[kk+tig  ][n0+gid]);
                bfr[j][1] = __float_as_uint(Bs[kk+tig+4][n0+gid]);
            }
            #pragma unroll
            for (int i = 0; i < 2; i++)
                #pragma unroll
                for (int j = 0; j < 8; j++) {
                    asm volatile(
                        "mma.sync.aligned.m16n8k8.row.col.f32.tf32.tf32.f32 "
                        "{%0,%1,%2,%3}, {%4,%5,%6,%7}, {%8,%9}, {%0,%1,%2,%3};"
                        : "+f"(c[i][j][0]), "+f"(c[i][j][1]),
                          "+f"(c[i][j][2]), "+f"(c[i][j][3])
                        : "r"(a[i][0]), "r"(a[i][1]), "r"(a[i][2]), "r"(a[i][3]),
                          "r"(bfr[j][0]), "r"(bfr[j][1]));
                }
        }
        __syncthreads();
    }

    // Epilogue: c frag layout: rows gid / gid+8, cols tig*2, tig*2+1
    #pragma unroll
    for (int i = 0; i < 2; i++) {
        #pragma unroll
        for (int j = 0; j < 8; j++) {
            int gc = col0 + wn + j*8 + tig*2;
            #pragma unroll
            for (int h = 0; h < 2; h++) {
                int gr = row0 + wm + i*16 + gid + h*8;
                float2 v = make_float2(c[i][j][h*2], c[i][j][h*2+1]);
                if (MODE == 2) {
                    if (gc+0 > gr) v.x = 0.f;
                    if (gc+1 > gr) v.y = 0.f;
                }
                *(float2*)&Cb[(size_t)gr*NN + gc] = v;
            }
        }
    }
}

// ---------------------------------------------------------------------------
// Layer 4 (row 1023 only) + logits
// ---------------------------------------------------------------------------
__global__ void l4_q(const float* __restrict__ R, const int* __restrict__ tok,
                     const float* __restrict__ P, float* __restrict__ q) {
    int b = blockIdx.x;
    __shared__ float rsh[NN];
    __shared__ int   tsh[NN];
    for (int i = threadIdx.x; i < NN; i += blockDim.x) {
        rsh[i] = P[((size_t)b*NN + (NN-1))*NN + i];
        tsh[i] = tok[b*NN + i];
    }
    __syncthreads();
    int d0 = threadIdx.x, d1 = d0 + 512, d2 = d0 + 1024;
    float a0 = 0.f, a1 = 0.f, a2 = 0.f;
    for (int m = 0; m < NN; m++) {
        float r = rsh[m];
        const float* Rt = R + (size_t)tsh[m]*DD;
        const float* Rp = R + (size_t)(VV + m)*DD;
        a0 += r * (Rt[d0] + Rp[d0]);
        a1 += r * (Rt[d1] + Rp[d1]);
        a2 += r * (Rt[d2] + Rp[d2]);
    }
    q[b*DD + d0] = a0; q[b*DD + d1] = a1; q[b*DD + d2] = a2;
}

__global__ void l4_u(const float* __restrict__ q, const int* __restrict__ tok,
                     float* __restrict__ u) {
    int b = blockIdx.x;
    for (int m = threadIdx.x; m < NN; m += blockDim.x) {
        int t = tok[b*NN + m];
        u[b*NN + m] = q[b*DD + t] + q[b*DD + VV + m];
    }
}

__global__ void l4_srow(const float* __restrict__ u, const float* __restrict__ P,
                        float* __restrict__ srow) {
    int b = blockIdx.y;
    __shared__ float ush[NN];
    for (int i = threadIdx.x; i < NN; i += 256) ush[i] = u[b*NN + i];
    __syncthreads();
    int row  = blockIdx.x * 8 + (threadIdx.x >> 5);
    int lane = threadIdx.x & 31;
    const float* Prow = P + ((size_t)b*NN + row)*NN;
    float acc = 0.f;
    for (int k = lane; k < NN; k += 32) acc += ush[k] * Prow[k];
    for (int o = 16; o; o >>= 1) acc += __shfl_down_sync(0xffffffffu, acc, o);
    if (lane == 0) srow[b*NN + row] = acc;
}

__global__ void l4_softmax(const float* __restrict__ s, float* __restrict__ a) {
    int b = blockIdx.x;
    __shared__ float red[256];
    float mx = -1e30f;
    for (int m = threadIdx.x; m < NN; m += 256) mx = fmaxf(mx, s[b*NN + m]);
    red[threadIdx.x] = mx; __syncthreads();
    for (int st = 128; st > 0; st >>= 1) {
        if (threadIdx.x < st) red[threadIdx.x] = fmaxf(red[threadIdx.x], red[threadIdx.x+st]);
        __syncthreads();
    }
    mx = red[0]; __syncthreads();
    float sum = 0.f;
    for (int m = threadIdx.x; m < NN; m += 256) {
        float e = __expf(s[b*NN + m] - mx);
        a[b*NN + m] = e; sum += e;
    }
    red[threadIdx.x] = sum; __syncthreads();
    for (int st = 128; st > 0; st >>= 1) {
        if (threadIdx.x < st) red[threadIdx.x] += red[threadIdx.x+st];
        __syncthreads();
    }
    float inv = 1.f / red[0];
    for (int m = threadIdx.x; m < NN; m += 256) a[b*NN + m] *= inv;
}

__global__ void l4_p(const float* __restrict__ a, const float* __restrict__ P,
                     float* __restrict__ p) {
    int b = blockIdx.y;
    int k = blockIdx.x * 256 + threadIdx.x;
    __shared__ float ash[NN];
    for (int i = threadIdx.x; i < NN; i += 256) ash[i] = a[b*NN + i];
    __syncthreads();
    float acc = 0.f;
    for (int m = 0; m < NN; m++) acc += ash[m] * P[((size_t)b*NN + m)*NN + k];
    p[b*NN + k] = acc;
}

__global__ void l4_c(const int* __restrict__ tok, const float* __restrict__ p,
                     float* __restrict__ c) {
    int b = blockIdx.x;
    __shared__ float psh[NN];
    __shared__ int   tsh[NN];
    for (int i = threadIdx.x; i < NN; i += blockDim.x) {
        psh[i] = p[b*NN + i];
        tsh[i] = tok[b*NN + i];
    }
    __syncthreads();
    int w = threadIdx.x;  // blockDim.x == 512 == VV
    float acc = 0.f;
    for (int m = 0; m < NN; m++)
        if (tsh[m] == w) acc += psh[m];
    c[b*VV + w] = acc;
}

__global__ void l4_logits(const float* __restrict__ c, const float* __restrict__ p,
                          const float* __restrict__ U, float* __restrict__ out) {
    int b = blockIdx.y;
    __shared__ float hsh[DD];
    for (int i = threadIdx.x; i < VV; i += 256) hsh[i]      = c[b*VV + i];
    for (int i = threadIdx.x; i < NN; i += 256) hsh[VV + i] = p[b*NN + i];
    __syncthreads();
    int wid = threadIdx.x >> 5, lane = threadIdx.x & 31;
    int v = blockIdx.x * 8 + wid;
    const float* Ur = U + (size_t)v*DD;
    float acc = 0.f;
    for (int j = lane; j < DD; j += 32) acc += hsh[j] * Ur[j];
    for (int o = 16; o; o >>= 1) acc += __shfl_down_sync(0xffffffffu, acc, o);
    if (lane == 0) out[b*VV + v] = acc;
}

// ---------------------------------------------------------------------------
extern "C" void kernel_launch(void* const* d_in, const int* in_sizes, int n_in,
                              void* d_out, int out_size) {
    const int*   tok = (const int*)  d_in[0];
    const float* R   = (const float*)d_in[1];
    const float* U   = (const float*)d_in[2];
    float*       out = (float*)d_out;

    float *S, *P, *T, *A, *PN, *q, *u, *sr, *a, *p, *c;
    cudaGetSymbolAddress((void**)&S,  g_S);
    cudaGetSymbolAddress((void**)&P,  g_P);
    cudaGetSymbolAddress((void**)&T,  g_T);
    cudaGetSymbolAddress((void**)&A,  g_A);
    cudaGetSymbolAddress((void**)&PN, g_PN);
    cudaGetSymbolAddress((void**)&q,  g_q);
    cudaGetSymbolAddress((void**)&u,  g_u);
    cudaGetSymbolAddress((void**)&sr, g_sr);
    cudaGetSymbolAddress((void**)&a,  g_a);
    cudaGetSymbolAddress((void**)&p,  g_p);
    cudaGetSymbolAddress((void**)&c,  g_c);

    dim3 gRow(NN, BB), gT(8, 8, BB);
    const size_t RS = (size_t)DD*DD;

    // Layer 1: P2 = A1 = softmax(S1)  (P1 = I)
    gather_S      <<<gRow, 256>>>(R + 0*RS, tok, S);
    softmax_causal<<<gRow, 256>>>(S, P);

    // Layer 2: scores = P*S2*P^T ; A2 = softmax ; P3 = A2*P
    gather_S      <<<gRow, 256>>>(R + 1*RS, tok, S);
    gemm_tf32<0>  <<<gT, 256>>>(P, S, T);
    gemm_tf32<1>  <<<gT, 256>>>(T, P, A);
    softmax_causal<<<gRow, 256>>>(A, A);
    gemm_tf32<2>  <<<gT, 256>>>(A, P, PN);

    // Layer 3: same with P3 (in PN) -> P4 (into P)
    gather_S      <<<gRow, 256>>>(R + 2*RS, tok, S);
    gemm_tf32<0>  <<<gT, 256>>>(PN, S, T);
    gemm_tf32<1>  <<<gT, 256>>>(T, PN, A);
    softmax_causal<<<gRow, 256>>>(A, A);
    gemm_tf32<2>  <<<gT, 256>>>(A, PN, P);

    // Layer 4 (row 1023 only) + logits
    l4_q      <<<BB, 512>>>(R + 3*RS, tok, P, q);
    l4_u      <<<BB, 256>>>(q, tok, u);
    l4_srow   <<<dim3(128, BB), 256>>>(u, P, sr);
    l4_softmax<<<BB, 256>>>(sr, a);
    l4_p      <<<dim3(4, BB), 256>>>(a, P, p);
    l4_c      <<<BB, 512>>>(tok, p, c);
    l4_logits <<<dim3(64, BB), 256>>>(c, p, U, out);
}

// round 5
// speedup vs baseline: 2.0136x; 1.2217x over previous
#include <cuda_runtime.h>
#include <cuda_bf16.h>
#include <cstdint>

// Problem constants
#define BB 32
#define NN 1024
#define VV 512
#define DD 1536

// Scratch buffers (allocation-free rule: __device__ globals)
__device__ float g_S [(size_t)BB*NN*NN];
__device__ float g_P [(size_t)BB*NN*NN];
__device__ float g_T [(size_t)BB*NN*NN];
__device__ float g_A [(size_t)BB*NN*NN];
__device__ float g_PN[(size_t)BB*NN*NN];
__device__ float g_q [BB*DD];
__device__ float g_u [BB*NN];
__device__ float g_sr[BB*NN];
__device__ float g_a [BB*NN];
__device__ float g_p [BB*NN];
__device__ float g_c [BB*VV];

// RNA round-to-tf32 (unbiased; RZ truncation in raw MMA is biased and fails 1e-3)
__device__ __forceinline__ uint32_t tf32r(float x) {
    uint32_t u;
    asm("cvt.rna.tf32.f32 %0, %1;" : "=r"(u) : "f"(x));
    return u;
}

// ---------------------------------------------------------------------------
// Fused layer 1: row m of S1 built in smem, softmaxed, written once.
// ---------------------------------------------------------------------------
__global__ void gather_softmax1(const float* __restrict__ R, const int* __restrict__ tok,
                                float* __restrict__ P) {
    int b = blockIdx.y, m = blockIdx.x;
    __shared__ float Wsh[DD];
    __shared__ int   tsh[NN];
    __shared__ float red[256];
    const int* tb = tok + b*NN;
    int tm = tb[m];
    for (int d = threadIdx.x; d < DD; d += 256)
        Wsh[d] = R[(size_t)tm*DD + d] + R[(size_t)(VV + m)*DD + d];
    for (int i = threadIdx.x; i < NN; i += 256) tsh[i] = tb[i];
    __syncthreads();
    int len = m + 1;
    float mx = -1e30f;
    for (int mp = threadIdx.x; mp < len; mp += 256)
        mx = fmaxf(mx, Wsh[tsh[mp]] + Wsh[VV + mp]);
    red[threadIdx.x] = mx; __syncthreads();
    for (int s = 128; s > 0; s >>= 1) {
        if (threadIdx.x < s) red[threadIdx.x] = fmaxf(red[threadIdx.x], red[threadIdx.x+s]);
        __syncthreads();
    }
    mx = red[0]; __syncthreads();
    float sum = 0.f;
    for (int mp = threadIdx.x; mp < len; mp += 256)
        sum += __expf(Wsh[tsh[mp]] + Wsh[VV + mp] - mx);
    red[threadIdx.x] = sum; __syncthreads();
    for (int s = 128; s > 0; s >>= 1) {
        if (threadIdx.x < s) red[threadIdx.x] += red[threadIdx.x+s];
        __syncthreads();
    }
    float inv = 1.f / red[0];
    float* arow = P + ((size_t)b*NN + m)*NN;
    for (int mp = threadIdx.x; mp < len; mp += 256)
        arow[mp] = __expf(Wsh[tsh[mp]] + Wsh[VV + mp] - mx) * inv;
    for (int mp = len + threadIdx.x; mp < NN; mp += 256) arow[mp] = 0.f;
}

// ---------------------------------------------------------------------------
// S_k[m,m'] = W[m, t_m'] + W[m, V+m'] for layers 2,3 (feeds GEMM)
// ---------------------------------------------------------------------------
__global__ void gather_S(const float* __restrict__ R, const int* __restrict__ tok,
                         float* __restrict__ S) {
    int b = blockIdx.y, m = blockIdx.x;
    __shared__ float Wsh[DD];
    __shared__ int   tsh[NN];
    const int* tb = tok + b*NN;
    int tm = tb[m];
    for (int d = threadIdx.x; d < DD; d += blockDim.x)
        Wsh[d] = R[(size_t)tm*DD + d] + R[(size_t)(VV + m)*DD + d];
    for (int i = threadIdx.x; i < NN; i += blockDim.x) tsh[i] = tb[i];
    __syncthreads();
    float* Srow = S + ((size_t)b*NN + m)*NN;
    for (int mp = threadIdx.x; mp < NN; mp += blockDim.x)
        Srow[mp] = Wsh[tsh[mp]] + Wsh[VV + mp];
}

// ---------------------------------------------------------------------------
// Causal row softmax (in-place safe)
// ---------------------------------------------------------------------------
__global__ void softmax_causal(const float* __restrict__ S, float* __restrict__ A) {
    int b = blockIdx.y, n = blockIdx.x;
    const float* srow = S + ((size_t)b*NN + n)*NN;
    float*       arow = A + ((size_t)b*NN + n)*NN;
    int len = n + 1;
    __shared__ float red[256];
    float mx = -1e30f;
    for (int m = threadIdx.x; m < len; m += 256) mx = fmaxf(mx, srow[m]);
    red[threadIdx.x] = mx; __syncthreads();
    for (int s = 128; s > 0; s >>= 1) {
        if (threadIdx.x < s) red[threadIdx.x] = fmaxf(red[threadIdx.x], red[threadIdx.x+s]);
        __syncthreads();
    }
    mx = red[0]; __syncthreads();
    float sum = 0.f;
    for (int m = threadIdx.x; m < len; m += 256) {
        float e = __expf(srow[m] - mx);
        arow[m] = e; sum += e;
    }
    red[threadIdx.x] = sum; __syncthreads();
    for (int s = 128; s > 0; s >>= 1) {
        if (threadIdx.x < s) red[threadIdx.x] += red[threadIdx.x+s];
        __syncthreads();
    }
    float inv = 1.f / red[0];
    for (int m = threadIdx.x; m < len; m += 256) arow[m] *= inv;
    for (int m = len + threadIdx.x; m < NN; m += 256) arow[m] = 0.f;
}

// ---------------------------------------------------------------------------
// Batched 1024^3 GEMM, tf32 mma.sync m16n8k8, cp.async double-buffered.
// RNA tf32 conversion applied at fragment-load (registers, post-LDS).
// 128x128 block tile, 8 warps 4(m)x2(n), warp tile 32x64.
// MODE 0: C = A*B      k in [0,(bi+1)*128)         all tiles
// MODE 1: C = A*B^T    k in [0,(bj+1)*128)         tiles j<=i
// MODE 2: C = A*B      k in [bj*128,(bi+1)*128)    tiles j<=i, zero upper
// ---------------------------------------------------------------------------
template<int MODE>
__global__ void __launch_bounds__(256)
gemm_tf32(const float* __restrict__ Ag, const float* __restrict__ Bg,
          float* __restrict__ Cg) {
    int bi = blockIdx.y, bj = blockIdx.x, b = blockIdx.z;
    if (MODE != 0 && bj > bi) return;
    const float* Ab = Ag + (size_t)b*NN*NN;
    const float* Bb = Bg + (size_t)b*NN*NN;
    float*       Cb = Cg + (size_t)b*NN*NN;
    int k0 = (MODE == 2) ? bj*128 : 0;
    int k1 = (MODE == 1) ? (bj+1)*128 : (bi+1)*128;

    constexpr int ASTR = 20;                         // [m][k] row stride
    constexpr int BSZ  = (MODE == 1) ? 128*ASTR : 16*132;
    __shared__ __align__(16) float As[2][128*ASTR];  // A[m][k]
    __shared__ __align__(16) float Bs[2][BSZ];       // mode1: B[n][k]; else B[k][n] str 132

    int tid  = threadIdx.x;
    int wid  = tid >> 5, lane = tid & 31;
    int gid  = lane >> 2, tig = lane & 3;
    int wm   = (wid & 3) * 32;
    int wn   = (wid >> 2) * 64;
    int row0 = bi*128, col0 = bj*128;

    float c[2][8][4] = {};

    auto load_stage = [&](int s, int kb) {
        #pragma unroll
        for (int h = 0; h < 2; h++) {            // A tile: 128 x 16 floats
            int chunk = tid + 256*h;
            int r = chunk >> 2, c4 = (chunk & 3) * 4;
            uint32_t dst = (uint32_t)__cvta_generic_to_shared(&As[s][r*ASTR + c4]);
            const float* src = &Ab[(size_t)(row0 + r)*NN + kb + c4];
            asm volatile("cp.async.ca.shared.global [%0], [%1], 16;\n" :: "r"(dst), "l"(src));
        }
        if (MODE == 1) {                         // B tile: 128 rows (n) x 16 (k)
            #pragma unroll
            for (int h = 0; h < 2; h++) {
                int chunk = tid + 256*h;
                int r = chunk >> 2, c4 = (chunk & 3) * 4;
                uint32_t dst = (uint32_t)__cvta_generic_to_shared(&Bs[s][r*ASTR + c4]);
                const float* src = &Bb[(size_t)(col0 + r)*NN + kb + c4];
                asm volatile("cp.async.ca.shared.global [%0], [%1], 16;\n" :: "r"(dst), "l"(src));
            }
        } else {                                 // B tile: 16 rows (k) x 128 (n)
            #pragma unroll
            for (int h = 0; h < 2; h++) {
                int chunk = tid + 256*h;
                int r = chunk >> 5, c4 = (chunk & 31) * 4;
                uint32_t dst = (uint32_t)__cvta_generic_to_shared(&Bs[s][r*132 + c4]);
                const float* src = &Bb[(size_t)(kb + r)*NN + col0 + c4];
                asm volatile("cp.async.ca.shared.global [%0], [%1], 16;\n" :: "r"(dst), "l"(src));
            }
        }
    };

    load_stage(0, k0);
    asm volatile("cp.async.commit_group;\n");
    int s = 0;
    for (int kb = k0; kb < k1; kb += 16, s ^= 1) {
        if (kb + 16 < k1) load_stage(s ^ 1, kb + 16);
        asm volatile("cp.async.commit_group;\n");
        asm volatile("cp.async.wait_group 1;\n");
        __syncthreads();
        const float* Ac = As[s];
        const float* Bc = Bs[s];
        #pragma unroll
        for (int kk = 0; kk < 16; kk += 8) {
            uint32_t a[2][4];
            #pragma unroll
            for (int i = 0; i < 2; i++) {
                int m0 = wm + i*16;
                a[i][0] = tf32r(Ac[(m0+gid  )*ASTR + kk+tig  ]);
                a[i][1] = tf32r(Ac[(m0+gid+8)*ASTR + kk+tig  ]);
                a[i][2] = tf32r(Ac[(m0+gid  )*ASTR + kk+tig+4]);
                a[i][3] = tf32r(Ac[(m0+gid+8)*ASTR + kk+tig+4]);
            }
            uint32_t bfr[8][2];
            #pragma unroll
            for (int j = 0; j < 8; j++) {
                int n0 = wn + j*8;
                if (MODE == 1) {
                    bfr[j][0] = tf32r(Bc[(n0+gid)*ASTR + kk+tig  ]);
                    bfr[j][1] = tf32r(Bc[(n0+gid)*ASTR + kk+tig+4]);
                } else {
                    bfr[j][0] = tf32r(Bc[(kk+tig  )*132 + n0+gid]);
                    bfr[j][1] = tf32r(Bc[(kk+tig+4)*132 + n0+gid]);
                }
            }
            #pragma unroll
            for (int i = 0; i < 2; i++)
                #pragma unroll
                for (int j = 0; j < 8; j++) {
                    asm volatile(
                        "mma.sync.aligned.m16n8k8.row.col.f32.tf32.tf32.f32 "
                        "{%0,%1,%2,%3}, {%4,%5,%6,%7}, {%8,%9}, {%0,%1,%2,%3};"
                        : "+f"(c[i][j][0]), "+f"(c[i][j][1]),
                          "+f"(c[i][j][2]), "+f"(c[i][j][3])
                        : "r"(a[i][0]), "r"(a[i][1]), "r"(a[i][2]), "r"(a[i][3]),
                          "r"(bfr[j][0]), "r"(bfr[j][1]));
                }
        }
        __syncthreads();
    }

    #pragma unroll
    for (int i = 0; i < 2; i++) {
        #pragma unroll
        for (int j = 0; j < 8; j++) {
            int gc = col0 + wn + j*8 + tig*2;
            #pragma unroll
            for (int h = 0; h < 2; h++) {
                int gr = row0 + wm + i*16 + gid + h*8;
                float2 v = make_float2(c[i][j][h*2], c[i][j][h*2+1]);
                if (MODE == 2) {
                    if (gc+0 > gr) v.x = 0.f;
                    if (gc+1 > gr) v.y = 0.f;
                }
                *(float2*)&Cb[(size_t)gr*NN + gc] = v;
            }
        }
    }
}

// ---------------------------------------------------------------------------
// Layer 4 (row 1023 only) + logits
// ---------------------------------------------------------------------------
__global__ void l4_q(const float* __restrict__ R, const int* __restrict__ tok,
                     const float* __restrict__ P, float* __restrict__ q) {
    int b = blockIdx.x;
    __shared__ float rsh[NN];
    __shared__ int   tsh[NN];
    for (int i = threadIdx.x; i < NN; i += blockDim.x) {
        rsh[i] = P[((size_t)b*NN + (NN-1))*NN + i];
        tsh[i] = tok[b*NN + i];
    }
    __syncthreads();
    int d0 = threadIdx.x, d1 = d0 + 512, d2 = d0 + 1024;
    float a0 = 0.f, a1 = 0.f, a2 = 0.f;
    for (int m = 0; m < NN; m++) {
        float r = rsh[m];
        const float* Rt = R + (size_t)tsh[m]*DD;
        const float* Rp = R + (size_t)(VV + m)*DD;
        a0 += r * (Rt[d0] + Rp[d0]);
        a1 += r * (Rt[d1] + Rp[d1]);
        a2 += r * (Rt[d2] + Rp[d2]);
    }
    q[b*DD + d0] = a0; q[b*DD + d1] = a1; q[b*DD + d2] = a2;
}

__global__ void l4_u(const float* __restrict__ q, const int* __restrict__ tok,
                     float* __restrict__ u) {
    int b = blockIdx.x;
    for (int m = threadIdx.x; m < NN; m += blockDim.x) {
        int t = tok[b*NN + m];
        u[b*NN + m] = q[b*DD + t] + q[b*DD + VV + m];
    }
}

__global__ void l4_srow(const float* __restrict__ u, const float* __restrict__ P,
                        float* __restrict__ srow) {
    int b = blockIdx.y;
    __shared__ float ush[NN];
    for (int i = threadIdx.x; i < NN; i += 256) ush[i] = u[b*NN + i];
    __syncthreads();
    int row  = blockIdx.x * 8 + (threadIdx.x >> 5);
    int lane = threadIdx.x & 31;
    const float* Prow = P + ((size_t)b*NN + row)*NN;
    float acc = 0.f;
    for (int k = lane; k < NN; k += 32) acc += ush[k] * Prow[k];
    for (int o = 16; o; o >>= 1) acc += __shfl_down_sync(0xffffffffu, acc, o);
    if (lane == 0) srow[b*NN + row] = acc;
}

__global__ void l4_softmax(const float* __restrict__ s, float* __restrict__ a) {
    int b = blockIdx.x;
    __shared__ float red[256];
    float mx = -1e30f;
    for (int m = threadIdx.x; m < NN; m += 256) mx = fmaxf(mx, s[b*NN + m]);
    red[threadIdx.x] = mx; __syncthreads();
    for (int st = 128; st > 0; st >>= 1) {
        if (threadIdx.x < st) red[threadIdx.x] = fmaxf(red[threadIdx.x], red[threadIdx.x+st]);
        __syncthreads();
    }
    mx = red[0]; __syncthreads();
    float sum = 0.f;
    for (int m = threadIdx.x; m < NN; m += 256) {
        float e = __expf(s[b*NN + m] - mx);
        a[b*NN + m] = e; sum += e;
    }
    red[threadIdx.x] = sum; __syncthreads();
    for (int st = 128; st > 0; st >>= 1) {
        if (threadIdx.x < st) red[threadIdx.x] += red[threadIdx.x+st];
        __syncthreads();
    }
    float inv = 1.f / red[0];
    for (int m = threadIdx.x; m < NN; m += 256) a[b*NN + m] *= inv;
}

__global__ void l4_p(const float* __restrict__ a, const float* __restrict__ P,
                     float* __restrict__ p) {
    int b = blockIdx.y;
    int k = blockIdx.x * 256 + threadIdx.x;
    __shared__ float ash[NN];
    for (int i = threadIdx.x; i < NN; i += 256) ash[i] = a[b*NN + i];
    __syncthreads();
    float acc = 0.f;
    for (int m = 0; m < NN; m++) acc += ash[m] * P[((size_t)b*NN + m)*NN + k];
    p[b*NN + k] = acc;
}

__global__ void l4_c(const int* __restrict__ tok, const float* __restrict__ p,
                     float* __restrict__ c) {
    int b = blockIdx.x;
    __shared__ float psh[NN];
    __shared__ int   tsh[NN];
    for (int i = threadIdx.x; i < NN; i += blockDim.x) {
        psh[i] = p[b*NN + i];
        tsh[i] = tok[b*NN + i];
    }
    __syncthreads();
    int w = threadIdx.x;  // blockDim.x == 512 == VV
    float acc = 0.f;
    for (int m = 0; m < NN; m++)
        if (tsh[m] == w) acc += psh[m];
    c[b*VV + w] = acc;
}

__global__ void l4_logits(const float* __restrict__ c, const float* __restrict__ p,
                          const float* __restrict__ U, float* __restrict__ out) {
    int b = blockIdx.y;
    __shared__ float hsh[DD];
    for (int i = threadIdx.x; i < VV; i += 256) hsh[i]      = c[b*VV + i];
    for (int i = threadIdx.x; i < NN; i += 256) hsh[VV + i] = p[b*NN + i];
    __syncthreads();
    int wid = threadIdx.x >> 5, lane = threadIdx.x & 31;
    int v = blockIdx.x * 8 + wid;
    const float* Ur = U + (size_t)v*DD;
    float acc = 0.f;
    for (int j = lane; j < DD; j += 32) acc += hsh[j] * Ur[j];
    for (int o = 16; o; o >>= 1) acc += __shfl_down_sync(0xffffffffu, acc, o);
    if (lane == 0) out[b*VV + v] = acc;
}

// ---------------------------------------------------------------------------
extern "C" void kernel_launch(void* const* d_in, const int* in_sizes, int n_in,
                              void* d_out, int out_size) {
    const int*   tok = (const int*)  d_in[0];
    const float* R   = (const float*)d_in[1];
    const float* U   = (const float*)d_in[2];
    float*       out = (float*)d_out;

    float *S, *P, *T, *A, *PN, *q, *u, *sr, *a, *p, *c;
    cudaGetSymbolAddress((void**)&S,  g_S);
    cudaGetSymbolAddress((void**)&P,  g_P);
    cudaGetSymbolAddress((void**)&T,  g_T);
    cudaGetSymbolAddress((void**)&A,  g_A);
    cudaGetSymbolAddress((void**)&PN, g_PN);
    cudaGetSymbolAddress((void**)&q,  g_q);
    cudaGetSymbolAddress((void**)&u,  g_u);
    cudaGetSymbolAddress((void**)&sr, g_sr);
    cudaGetSymbolAddress((void**)&a,  g_a);
    cudaGetSymbolAddress((void**)&p,  g_p);
    cudaGetSymbolAddress((void**)&c,  g_c);

    dim3 gRow(NN, BB), gT(8, 8, BB);
    const size_t RS = (size_t)DD*DD;

    // Layer 1 fused: P2 = softmax(S1) written directly
    gather_softmax1<<<gRow, 256>>>(R + 0*RS, tok, P);

    // Layer 2: scores = P*S2*P^T ; A2 = softmax ; P3 = A2*P
    gather_S      <<<gRow, 256>>>(R + 1*RS, tok, S);
    gemm_tf32<0>  <<<gT, 256>>>(P, S, T);
    gemm_tf32<1>  <<<gT, 256>>>(T, P, A);
    softmax_causal<<<gRow, 256>>>(A, A);
    gemm_tf32<2>  <<<gT, 256>>>(A, P, PN);

    // Layer 3: same with P3 (in PN) -> P4 (into P)
    gather_S      <<<gRow, 256>>>(R + 2*RS, tok, S);
    gemm_tf32<0>  <<<gT, 256>>>(PN, S, T);
    gemm_tf32<1>  <<<gT, 256>>>(T, PN, A);
    softmax_causal<<<gRow, 256>>>(A, A);
    gemm_tf32<2>  <<<gT, 256>>>(A, PN, P);

    // Layer 4 (row 1023 only) + logits
    l4_q      <<<BB, 512>>>(R + 3*RS, tok, P, q);
    l4_u      <<<BB, 256>>>(q, tok, u);
    l4_srow   <<<dim3(128, BB), 256>>>(u, P, sr);
    l4_softmax<<<BB, 256>>>(sr, a);
    l4_p      <<<dim3(4, BB), 256>>>(a, P, p);
    l4_c      <<<BB, 512>>>(tok, p, c);
    l4_logits <<<dim3(64, BB), 256>>>(c, p, U, out);
}

// round 6
// speedup vs baseline: 2.2128x; 1.0990x over previous
#include <cuda_runtime.h>
#include <cuda_bf16.h>
#include <cstdint>

// Problem constants
#define BB 32
#define NN 1024
#define VV 512
#define DD 1536

// Scratch buffers (allocation-free rule: __device__ globals)
__device__ float g_S [(size_t)BB*NN*NN];
__device__ float g_P [(size_t)BB*NN*NN];
__device__ float g_T [(size_t)BB*NN*NN];
__device__ float g_A [(size_t)BB*NN*NN];
__device__ float g_PN[(size_t)BB*NN*NN];
__device__ float g_q [BB*DD];
__device__ float g_u [BB*NN];
__device__ float g_sr[BB*NN];
__device__ float g_a [BB*NN];
__device__ float g_p [BB*NN];
__device__ float g_c [BB*VV];

// RNA round-to-tf32 (unbiased). Applied at PRODUCER time so GEMMs feed raw
// smem bits into mma (whose internal RZ truncation is then the identity).
__device__ __forceinline__ float tf32f(float x) {
    uint32_t u;
    asm("cvt.rna.tf32.f32 %0, %1;" : "=r"(u) : "f"(x));
    return __uint_as_float(u);
}

// ---------------------------------------------------------------------------
// Fused layer 1: row m of S1 built in smem, softmaxed, written (tf32-rounded).
// ---------------------------------------------------------------------------
__global__ void gather_softmax1(const float* __restrict__ R, const int* __restrict__ tok,
                                float* __restrict__ P) {
    int b = blockIdx.y, m = blockIdx.x;
    __shared__ float Wsh[DD];
    __shared__ int   tsh[NN];
    __shared__ float red[256];
    const int* tb = tok + b*NN;
    int tm = tb[m];
    for (int d = threadIdx.x; d < DD; d += 256)
        Wsh[d] = R[(size_t)tm*DD + d] + R[(size_t)(VV + m)*DD + d];
    for (int i = threadIdx.x; i < NN; i += 256) tsh[i] = tb[i];
    __syncthreads();
    int len = m + 1;
    float mx = -1e30f;
    for (int mp = threadIdx.x; mp < len; mp += 256)
        mx = fmaxf(mx, Wsh[tsh[mp]] + Wsh[VV + mp]);
    red[threadIdx.x] = mx; __syncthreads();
    for (int s = 128; s > 0; s >>= 1) {
        if (threadIdx.x < s) red[threadIdx.x] = fmaxf(red[threadIdx.x], red[threadIdx.x+s]);
        __syncthreads();
    }
    mx = red[0]; __syncthreads();
    float sum = 0.f;
    for (int mp = threadIdx.x; mp < len; mp += 256)
        sum += __expf(Wsh[tsh[mp]] + Wsh[VV + mp] - mx);
    red[threadIdx.x] = sum; __syncthreads();
    for (int s = 128; s > 0; s >>= 1) {
        if (threadIdx.x < s) red[threadIdx.x] += red[threadIdx.x+s];
        __syncthreads();
    }
    float inv = 1.f / red[0];
    float* arow = P + ((size_t)b*NN + m)*NN;
    for (int mp = threadIdx.x; mp < len; mp += 256)
        arow[mp] = tf32f(__expf(Wsh[tsh[mp]] + Wsh[VV + mp] - mx) * inv);
    for (int mp = len + threadIdx.x; mp < NN; mp += 256) arow[mp] = 0.f;
}

// ---------------------------------------------------------------------------
// S_k[m,m'] (tf32-rounded; feeds GEMM B operand)
// ---------------------------------------------------------------------------
__global__ void gather_S(const float* __restrict__ R, const int* __restrict__ tok,
                         float* __restrict__ S) {
    int b = blockIdx.y, m = blockIdx.x;
    __shared__ float Wsh[DD];
    __shared__ int   tsh[NN];
    const int* tb = tok + b*NN;
    int tm = tb[m];
    for (int d = threadIdx.x; d < DD; d += blockDim.x)
        Wsh[d] = R[(size_t)tm*DD + d] + R[(size_t)(VV + m)*DD + d];
    for (int i = threadIdx.x; i < NN; i += blockDim.x) tsh[i] = tb[i];
    __syncthreads();
    float* Srow = S + ((size_t)b*NN + m)*NN;
    for (int mp = threadIdx.x; mp < NN; mp += blockDim.x)
        Srow[mp] = tf32f(Wsh[tsh[mp]] + Wsh[VV + mp]);
}

// ---------------------------------------------------------------------------
// Causal row softmax (in-place safe; output tf32-rounded — feeds gemm<2>)
// ---------------------------------------------------------------------------
__global__ void softmax_causal(const float* __restrict__ S, float* __restrict__ A) {
    int b = blockIdx.y, n = blockIdx.x;
    const float* srow = S + ((size_t)b*NN + n)*NN;
    float*       arow = A + ((size_t)b*NN + n)*NN;
    int len = n + 1;
    __shared__ float red[256];
    float mx = -1e30f;
    for (int m = threadIdx.x; m < len; m += 256) mx = fmaxf(mx, srow[m]);
    red[threadIdx.x] = mx; __syncthreads();
    for (int s = 128; s > 0; s >>= 1) {
        if (threadIdx.x < s) red[threadIdx.x] = fmaxf(red[threadIdx.x], red[threadIdx.x+s]);
        __syncthreads();
    }
    mx = red[0]; __syncthreads();
    float sum = 0.f;
    for (int m = threadIdx.x; m < len; m += 256) {
        float e = __expf(srow[m] - mx);
        arow[m] = e; sum += e;
    }
    red[threadIdx.x] = sum; __syncthreads();
    for (int s = 128; s > 0; s >>= 1) {
        if (threadIdx.x < s) red[threadIdx.x] += red[threadIdx.x+s];
        __syncthreads();
    }
    float inv = 1.f / red[0];
    for (int m = threadIdx.x; m < len; m += 256) arow[m] = tf32f(arow[m] * inv);
    for (int m = len + threadIdx.x; m < NN; m += 256) arow[m] = 0.f;
}

// ---------------------------------------------------------------------------
// Batched 1024^3 GEMM, tf32 mma.sync m16n8k8; 3-stage cp.async pipeline,
// one __syncthreads per k16 slab. Inputs pre-rounded to tf32 (no CVT here).
// 128x128 block tile, 8 warps 4(m)x2(n), warp tile 32x64.
// MODE 0: C = A*B      k in [0,(bi+1)*128)         all tiles
// MODE 1: C = A*B^T    k in [0,(bj+1)*128)         tiles j<=i
// MODE 2: C = A*B      k in [bj*128,(bi+1)*128)    tiles j<=i, zero upper
// ROUND: epilogue rounds output to tf32 (when C feeds a later GEMM).
// ---------------------------------------------------------------------------
#define ASTG (128*20)
template<int MODE>
struct BCfg { static constexpr int STR = 136, STG = 16*136; };
template<> struct BCfg<1> { static constexpr int STR = 20, STG = 128*20; };

template<int MODE, bool ROUND>
__global__ void __launch_bounds__(256)
gemm_tf32(const float* __restrict__ Ag, const float* __restrict__ Bg,
          float* __restrict__ Cg) {
    constexpr int BSTR = BCfg<MODE>::STR;
    constexpr int BSTG = BCfg<MODE>::STG;
    int bi = blockIdx.y, bj = blockIdx.x, b = blockIdx.z;
    if (MODE != 0 && bj > bi) return;
    const float* Ab = Ag + (size_t)b*NN*NN;
    const float* Bb = Bg + (size_t)b*NN*NN;
    float*       Cb = Cg + (size_t)b*NN*NN;
    int k0 = (MODE == 2) ? bj*128 : 0;
    int k1 = (MODE == 1) ? (bj+1)*128 : (bi+1)*128;

    extern __shared__ __align__(16) float sm[];
    float* As = sm;             // 3 stages of A[m][k], stride 20
    float* Bs = sm + 3*ASTG;    // 3 stages of B

    int tid  = threadIdx.x;
    int wid  = tid >> 5, lane = tid & 31;
    int gid  = lane >> 2, tig = lane & 3;
    int wm   = (wid & 3) * 32;
    int wn   = (wid >> 2) * 64;
    int row0 = bi*128, col0 = bj*128;

    float c[2][8][4] = {};

    auto load_stage = [&](int s, int kb) {
        float* Ad = As + s*ASTG;
        #pragma unroll
        for (int h = 0; h < 2; h++) {            // A: 128 x 16
            int chunk = tid + 256*h;
            int r = chunk >> 2, c4 = (chunk & 3) * 4;
            uint32_t dst = (uint32_t)__cvta_generic_to_shared(&Ad[r*20 + c4]);
            const float* src = &Ab[(size_t)(row0 + r)*NN + kb + c4];
            asm volatile("cp.async.ca.shared.global [%0], [%1], 16;\n" :: "r"(dst), "l"(src));
        }
        float* Bd = Bs + s*BSTG;
        if (MODE == 1) {                         // B: 128 rows (n) x 16 (k)
            #pragma unroll
            for (int h = 0; h < 2; h++) {
                int chunk = tid + 256*h;
                int r = chunk >> 2, c4 = (chunk & 3) * 4;
                uint32_t dst = (uint32_t)__cvta_generic_to_shared(&Bd[r*BSTR + c4]);
                const float* src = &Bb[(size_t)(col0 + r)*NN + kb + c4];
                asm volatile("cp.async.ca.shared.global [%0], [%1], 16;\n" :: "r"(dst), "l"(src));
            }
        } else {                                 // B: 16 rows (k) x 128 (n), stride 136
            #pragma unroll
            for (int h = 0; h < 2; h++) {
                int chunk = tid + 256*h;
                int r = chunk >> 5, c4 = (chunk & 31) * 4;
                uint32_t dst = (uint32_t)__cvta_generic_to_shared(&Bd[r*BSTR + c4]);
                const float* src = &Bb[(size_t)(kb + r)*NN + col0 + c4];
                asm volatile("cp.async.ca.shared.global [%0], [%1], 16;\n" :: "r"(dst), "l"(src));
            }
        }
    };

    auto compute = [&](int s) {
        const float* Ac = As + s*ASTG;
        const float* Bc = Bs + s*BSTG;
        #pragma unroll
        for (int kk = 0; kk < 16; kk += 8) {
            uint32_t a[2][4];
            #pragma unroll
            for (int i = 0; i < 2; i++) {
                int m0 = wm + i*16;
                a[i][0] = __float_as_uint(Ac[(m0+gid  )*20 + kk+tig  ]);
                a[i][1] = __float_as_uint(Ac[(m0+gid+8)*20 + kk+tig  ]);
                a[i][2] = __float_as_uint(Ac[(m0+gid  )*20 + kk+tig+4]);
                a[i][3] = __float_as_uint(Ac[(m0+gid+8)*20 + kk+tig+4]);
            }
            uint32_t bfr[8][2];
            #pragma unroll
            for (int j = 0; j < 8; j++) {
                int n0 = wn + j*8;
                if (MODE == 1) {
                    bfr[j][0] = __float_as_uint(Bc[(n0+gid)*BSTR + kk+tig  ]);
                    bfr[j][1] = __float_as_uint(Bc[(n0+gid)*BSTR + kk+tig+4]);
                } else {
                    bfr[j][0] = __float_as_uint(Bc[(kk+tig  )*BSTR + n0+gid]);
                    bfr[j][1] = __float_as_uint(Bc[(kk+tig+4)*BSTR + n0+gid]);
                }
            }
            #pragma unroll
            for (int i = 0; i < 2; i++)
                #pragma unroll
                for (int j = 0; j < 8; j++) {
                    asm volatile(
                        "mma.sync.aligned.m16n8k8.row.col.f32.tf32.tf32.f32 "
                        "{%0,%1,%2,%3}, {%4,%5,%6,%7}, {%8,%9}, {%0,%1,%2,%3};"
                        : "+f"(c[i][j][0]), "+f"(c[i][j][1]),
                          "+f"(c[i][j][2]), "+f"(c[i][j][3])
                        : "r"(a[i][0]), "r"(a[i][1]), "r"(a[i][2]), "r"(a[i][3]),
                          "r"(bfr[j][0]), "r"(bfr[j][1]));
                }
        }
    };

    int nslab = (k1 - k0) >> 4;                  // always >= 8
    load_stage(0, k0);
    asm volatile("cp.async.commit_group;\n");
    load_stage(1, k0 + 16);
    asm volatile("cp.async.commit_group;\n");

    int sc = 0, sl = 2;                          // compute stage / next load stage
    for (int t = 0; t < nslab - 1; t++) {
        asm volatile("cp.async.wait_group 1;\n");  // in-order: slab t is done
        __syncthreads();
        if (t + 2 < nslab) {
            load_stage(sl, k0 + (t+2)*16);
            asm volatile("cp.async.commit_group;\n");
            sl = (sl == 2) ? 0 : sl + 1;
        }
        compute(sc);
        sc = (sc == 2) ? 0 : sc + 1;
    }
    asm volatile("cp.async.wait_group 0;\n");
    __syncthreads();
    compute(sc);

    #pragma unroll
    for (int i = 0; i < 2; i++) {
        #pragma unroll
        for (int j = 0; j < 8; j++) {
            int gc = col0 + wn + j*8 + tig*2;
            #pragma unroll
            for (int h = 0; h < 2; h++) {
                int gr = row0 + wm + i*16 + gid + h*8;
                float2 v = make_float2(c[i][j][h*2], c[i][j][h*2+1]);
                if (ROUND) { v.x = tf32f(v.x); v.y = tf32f(v.y); }
                if (MODE == 2) {
                    if (gc+0 > gr) v.x = 0.f;
                    if (gc+1 > gr) v.y = 0.f;
                }
                *(float2*)&Cb[(size_t)gr*NN + gc] = v;
            }
        }
    }
}

// ---------------------------------------------------------------------------
// Layer 4 (row 1023 only) + logits
// ---------------------------------------------------------------------------
__global__ void l4_q(const float* __restrict__ R, const int* __restrict__ tok,
                     const float* __restrict__ P, float* __restrict__ q) {
    int b = blockIdx.x;
    __shared__ float rsh[NN];
    __shared__ int   tsh[NN];
    for (int i = threadIdx.x; i < NN; i += blockDim.x) {
        rsh[i] = P[((size_t)b*NN + (NN-1))*NN + i];
        tsh[i] = tok[b*NN + i];
    }
    __syncthreads();
    int d0 = threadIdx.x, d1 = d0 + 512, d2 = d0 + 1024;
    float a0 = 0.f, a1 = 0.f, a2 = 0.f;
    for (int m = 0; m < NN; m++) {
        float r = rsh[m];
        const float* Rt = R + (size_t)tsh[m]*DD;
        const float* Rp = R + (size_t)(VV + m)*DD;
        a0 += r * (Rt[d0] + Rp[d0]);
        a1 += r * (Rt[d1] + Rp[d1]);
        a2 += r * (Rt[d2] + Rp[d2]);
    }
    q[b*DD + d0] = a0; q[b*DD + d1] = a1; q[b*DD + d2] = a2;
}

__global__ void l4_u(const float* __restrict__ q, const int* __restrict__ tok,
                     float* __restrict__ u) {
    int b = blockIdx.x;
    for (int m = threadIdx.x; m < NN; m += blockDim.x) {
        int t = tok[b*NN + m];
        u[b*NN + m] = q[b*DD + t] + q[b*DD + VV + m];
    }
}

__global__ void l4_srow(const float* __restrict__ u, const float* __restrict__ P,
                        float* __restrict__ srow) {
    int b = blockIdx.y;
    __shared__ float ush[NN];
    for (int i = threadIdx.x; i < NN; i += 256) ush[i] = u[b*NN + i];
    __syncthreads();
    int row  = blockIdx.x * 8 + (threadIdx.x >> 5);
    int lane = threadIdx.x & 31;
    const float* Prow = P + ((size_t)b*NN + row)*NN;
    float acc = 0.f;
    for (int k = lane; k < NN; k += 32) acc += ush[k] * Prow[k];
    for (int o = 16; o; o >>= 1) acc += __shfl_down_sync(0xffffffffu, acc, o);
    if (lane == 0) srow[b*NN + row] = acc;
}

__global__ void l4_softmax(const float* __restrict__ s, float* __restrict__ a) {
    int b = blockIdx.x;
    __shared__ float red[256];
    float mx = -1e30f;
    for (int m = threadIdx.x; m < NN; m += 256) mx = fmaxf(mx, s[b*NN + m]);
    red[threadIdx.x] = mx; __syncthreads();
    for (int st = 128; st > 0; st >>= 1) {
        if (threadIdx.x < st) red[threadIdx.x] = fmaxf(red[threadIdx.x], red[threadIdx.x+st]);
        __syncthreads();
    }
    mx = red[0]; __syncthreads();
    float sum = 0.f;
    for (int m = threadIdx.x; m < NN; m += 256) {
        float e = __expf(s[b*NN + m] - mx);
        a[b*NN + m] = e; sum += e;
    }
    red[threadIdx.x] = sum; __syncthreads();
    for (int st = 128; st > 0; st >>= 1) {
        if (threadIdx.x < st) red[threadIdx.x] += red[threadIdx.x+st];
        __syncthreads();
    }
    float inv = 1.f / red[0];
    for (int m = threadIdx.x; m < NN; m += 256) a[b*NN + m] *= inv;
}

__global__ void l4_p(const float* __restrict__ a, const float* __restrict__ P,
                     float* __restrict__ p) {
    int b = blockIdx.y;
    int k = blockIdx.x * 256 + threadIdx.x;
    __shared__ float ash[NN];
    for (int i = threadIdx.x; i < NN; i += 256) ash[i] = a[b*NN + i];
    __syncthreads();
    float acc = 0.f;
    for (int m = 0; m < NN; m++) acc += ash[m] * P[((size_t)b*NN + m)*NN + k];
    p[b*NN + k] = acc;
}

__global__ void l4_c(const int* __restrict__ tok, const float* __restrict__ p,
                     float* __restrict__ c) {
    int b = blockIdx.x;
    __shared__ float psh[NN];
    __shared__ int   tsh[NN];
    for (int i = threadIdx.x; i < NN; i += blockDim.x) {
        psh[i] = p[b*NN + i];
        tsh[i] = tok[b*NN + i];
    }
    __syncthreads();
    int w = threadIdx.x;  // blockDim.x == 512 == VV
    float acc = 0.f;
    for (int m = 0; m < NN; m++)
        if (tsh[m] == w) acc += psh[m];
    c[b*VV + w] = acc;
}

__global__ void l4_logits(const float* __restrict__ c, const float* __restrict__ p,
                          const float* __restrict__ U, float* __restrict__ out) {
    int b = blockIdx.y;
    __shared__ float hsh[DD];
    for (int i = threadIdx.x; i < VV; i += 256) hsh[i]      = c[b*VV + i];
    for (int i = threadIdx.x; i < NN; i += 256) hsh[VV + i] = p[b*NN + i];
    __syncthreads();
    int wid = threadIdx.x >> 5, lane = threadIdx.x & 31;
    int v = blockIdx.x * 8 + wid;
    const float* Ur = U + (size_t)v*DD;
    float acc = 0.f;
    for (int j = lane; j < DD; j += 32) acc += hsh[j] * Ur[j];
    for (int o = 16; o; o >>= 1) acc += __shfl_down_sync(0xffffffffu, acc, o);
    if (lane == 0) out[b*VV + v] = acc;
}

// ---------------------------------------------------------------------------
extern "C" void kernel_launch(void* const* d_in, const int* in_sizes, int n_in,
                              void* d_out, int out_size) {
    const int*   tok = (const int*)  d_in[0];
    const float* R   = (const float*)d_in[1];
    const float* U   = (const float*)d_in[2];
    float*       out = (float*)d_out;

    float *S, *P, *T, *A, *PN, *q, *u, *sr, *a, *p, *c;
    cudaGetSymbolAddress((void**)&S,  g_S);
    cudaGetSymbolAddress((void**)&P,  g_P);
    cudaGetSymbolAddress((void**)&T,  g_T);
    cudaGetSymbolAddress((void**)&A,  g_A);
    cudaGetSymbolAddress((void**)&PN, g_PN);
    cudaGetSymbolAddress((void**)&q,  g_q);
    cudaGetSymbolAddress((void**)&u,  g_u);
    cudaGetSymbolAddress((void**)&sr, g_sr);
    cudaGetSymbolAddress((void**)&a,  g_a);
    cudaGetSymbolAddress((void**)&p,  g_p);
    cudaGetSymbolAddress((void**)&c,  g_c);

    // dynamic smem: 3 stages of (A + B)
    const int SM1 = (3*ASTG + 3*BCfg<1>::STG) * 4;   // 61440
    const int SM0 = (3*ASTG + 3*BCfg<0>::STG) * 4;   // 56832
    cudaFuncSetAttribute(gemm_tf32<0,true >, cudaFuncAttributeMaxDynamicSharedMemorySize, SM0);
    cudaFuncSetAttribute(gemm_tf32<1,false>, cudaFuncAttributeMaxDynamicSharedMemorySize, SM1);
    cudaFuncSetAttribute(gemm_tf32<2,true >, cudaFuncAttributeMaxDynamicSharedMemorySize, SM0);
    cudaFuncSetAttribute(gemm_tf32<2,false>, cudaFuncAttributeMaxDynamicSharedMemorySize, SM0);

    dim3 gRow(NN, BB), gT(8, 8, BB);
    const size_t RS = (size_t)DD*DD;

    // Layer 1 fused: P2 = softmax(S1), tf32-rounded
    gather_softmax1<<<gRow, 256>>>(R + 0*RS, tok, P);

    // Layer 2: scores = P*S2*P^T ; A2 = softmax ; P3 = A2*P
    gather_S          <<<gRow, 256>>>(R + 1*RS, tok, S);
    gemm_tf32<0,true ><<<gT, 256, SM0>>>(P, S, T);
    gemm_tf32<1,false><<<gT, 256, SM1>>>(T, P, A);
    softmax_causal    <<<gRow, 256>>>(A, A);
    gemm_tf32<2,true ><<<gT, 256, SM0>>>(A, P, PN);

    // Layer 3: same with P3 (in PN) -> P4 (into P, full fp32 for l4)
    gather_S          <<<gRow, 256>>>(R + 2*RS, tok, S);
    gemm_tf32<0,true ><<<gT, 256, SM0>>>(PN, S, T);
    gemm_tf32<1,false><<<gT, 256, SM1>>>(T, PN, A);
    softmax_causal    <<<gRow, 256>>>(A, A);
    gemm_tf32<2,false><<<gT, 256, SM0>>>(A, PN, P);

    // Layer 4 (row 1023 only) + logits
    l4_q      <<<BB, 512>>>(R + 3*RS, tok, P, q);
    l4_u      <<<BB, 256>>>(q, tok, u);
    l4_srow   <<<dim3(128, BB), 256>>>(u, P, sr);
    l4_softmax<<<BB, 256>>>(sr, a);
    l4_p      <<<dim3(4, BB), 256>>>(a, P, p);
    l4_c      <<<BB, 512>>>(tok, p, c);
    l4_logits <<<dim3(64, BB), 256>>>(c, p, U, out);
}

// round 7
// speedup vs baseline: 3.3087x; 1.4952x over previous
#include <cuda_runtime.h>
#include <cuda_bf16.h>
#include <cstdint>

// Problem constants
#define BB 32
#define NN 1024
#define VV 512
#define DD 1536

typedef __nv_bfloat16 bf16;

// Scratch buffers (allocation-free rule: __device__ globals). Big tensors bf16.
__device__ bf16  g_S [(size_t)BB*NN*NN];
__device__ bf16  g_P [(size_t)BB*NN*NN];
__device__ bf16  g_T [(size_t)BB*NN*NN];
__device__ bf16  g_A [(size_t)BB*NN*NN];
__device__ bf16  g_PN[(size_t)BB*NN*NN];
__device__ float g_q [BB*DD];
__device__ float g_u [BB*NN];
__device__ float g_sr[BB*NN];
__device__ float g_a [BB*NN];
__device__ float g_p [BB*NN];
__device__ float g_c [BB*VV];

// ---------------------------------------------------------------------------
// Fused layer 1: row m of S1 built in smem, softmaxed, written bf16.
// ---------------------------------------------------------------------------
__global__ void gather_softmax1(const float* __restrict__ R, const int* __restrict__ tok,
                                bf16* __restrict__ P) {
    int b = blockIdx.y, m = blockIdx.x;
    __shared__ float Wsh[DD];
    __shared__ int   tsh[NN];
    __shared__ float red[256];
    const int* tb = tok + b*NN;
    int tm = tb[m];
    for (int d = threadIdx.x; d < DD; d += 256)
        Wsh[d] = R[(size_t)tm*DD + d] + R[(size_t)(VV + m)*DD + d];
    for (int i = threadIdx.x; i < NN; i += 256) tsh[i] = tb[i];
    __syncthreads();
    int len = m + 1;
    float mx = -1e30f;
    for (int mp = threadIdx.x; mp < len; mp += 256)
        mx = fmaxf(mx, Wsh[tsh[mp]] + Wsh[VV + mp]);
    red[threadIdx.x] = mx; __syncthreads();
    for (int s = 128; s > 0; s >>= 1) {
        if (threadIdx.x < s) red[threadIdx.x] = fmaxf(red[threadIdx.x], red[threadIdx.x+s]);
        __syncthreads();
    }
    mx = red[0]; __syncthreads();
    float sum = 0.f;
    for (int mp = threadIdx.x; mp < len; mp += 256)
        sum += __expf(Wsh[tsh[mp]] + Wsh[VV + mp] - mx);
    red[threadIdx.x] = sum; __syncthreads();
    for (int s = 128; s > 0; s >>= 1) {
        if (threadIdx.x < s) red[threadIdx.x] += red[threadIdx.x+s];
        __syncthreads();
    }
    float inv = 1.f / red[0];
    bf16* arow = P + ((size_t)b*NN + m)*NN;
    for (int mp = threadIdx.x; mp < len; mp += 256)
        arow[mp] = __float2bfloat16(__expf(Wsh[tsh[mp]] + Wsh[VV + mp] - mx) * inv);
    for (int mp = len + threadIdx.x; mp < NN; mp += 256) arow[mp] = __float2bfloat16(0.f);
}

// ---------------------------------------------------------------------------
// S_k[m,m'] gathered, written bf16 (GEMM B operand)
// ---------------------------------------------------------------------------
__global__ void gather_S(const float* __restrict__ R, const int* __restrict__ tok,
                         bf16* __restrict__ S) {
    int b = blockIdx.y, m = blockIdx.x;
    __shared__ float Wsh[DD];
    __shared__ int   tsh[NN];
    const int* tb = tok + b*NN;
    int tm = tb[m];
    for (int d = threadIdx.x; d < DD; d += blockDim.x)
        Wsh[d] = R[(size_t)tm*DD + d] + R[(size_t)(VV + m)*DD + d];
    for (int i = threadIdx.x; i < NN; i += blockDim.x) tsh[i] = tb[i];
    __syncthreads();
    bf16* Srow = S + ((size_t)b*NN + m)*NN;
    for (int mp = threadIdx.x; mp < NN; mp += blockDim.x)
        Srow[mp] = __float2bfloat16(Wsh[tsh[mp]] + Wsh[VV + mp]);
}

// ---------------------------------------------------------------------------
// Causal row softmax, bf16 in/out. Exp recomputed in final pass (single rounding).
// ---------------------------------------------------------------------------
__global__ void softmax_causal(const bf16* __restrict__ S, bf16* __restrict__ A) {
    int b = blockIdx.y, n = blockIdx.x;
    const bf16* srow = S + ((size_t)b*NN + n)*NN;
    bf16*       arow = A + ((size_t)b*NN + n)*NN;
    int len = n + 1;
    __shared__ float red[256];
    float mx = -1e30f;
    for (int m = threadIdx.x; m < len; m += 256) mx = fmaxf(mx, __bfloat162float(srow[m]));
    red[threadIdx.x] = mx; __syncthreads();
    for (int s = 128; s > 0; s >>= 1) {
        if (threadIdx.x < s) red[threadIdx.x] = fmaxf(red[threadIdx.x], red[threadIdx.x+s]);
        __syncthreads();
    }
    mx = red[0]; __syncthreads();
    float sum = 0.f;
    for (int m = threadIdx.x; m < len; m += 256)
        sum += __expf(__bfloat162float(srow[m]) - mx);
    red[threadIdx.x] = sum; __syncthreads();
    for (int s = 128; s > 0; s >>= 1) {
        if (threadIdx.x < s) red[threadIdx.x] += red[threadIdx.x+s];
        __syncthreads();
    }
    float inv = 1.f / red[0];
    for (int m = threadIdx.x; m < len; m += 256)
        arow[m] = __float2bfloat16(__expf(__bfloat162float(srow[m]) - mx) * inv);
    for (int m = len + threadIdx.x; m < NN; m += 256) arow[m] = __float2bfloat16(0.f);
}

// ---------------------------------------------------------------------------
// Batched 1024^3 bf16 GEMM: mma.sync m16n8k16, ldmatrix fragments,
// 3-stage cp.async, k-slab 32. 128x128 tile, 8 warps 4(m)x2(n), warp 32x64.
// MODE 0: C = A*B      k in [0,(bi+1)*128)         all tiles
// MODE 1: C = A*B^T    k in [0,(bj+1)*128)         tiles j<=i
// MODE 2: C = A*B      k in [bj*128,(bi+1)*128)    tiles j<=i, zero upper
// Smem (halves): A[m][k] stride 40; B mode1 [n][k] stride 40; else [k][n] stride 136.
// ---------------------------------------------------------------------------
#define ASTG_H (128*40)
template<int MODE>
struct BC { static constexpr int STR = 136, STG = 32*136; };
template<> struct BC<1> { static constexpr int STR = 40, STG = 128*40; };

template<int MODE>
__global__ void __launch_bounds__(256)
gemm_bf16(const bf16* __restrict__ Ag, const bf16* __restrict__ Bg,
          bf16* __restrict__ Cg) {
    constexpr int BSTR = BC<MODE>::STR;
    constexpr int BSTG = BC<MODE>::STG;
    int bi = blockIdx.y, bj = blockIdx.x, b = blockIdx.z;
    if (MODE != 0 && bj > bi) return;
    const bf16* Ab = Ag + (size_t)b*NN*NN;
    const bf16* Bb = Bg + (size_t)b*NN*NN;
    bf16*       Cb = Cg + (size_t)b*NN*NN;
    int k0 = (MODE == 2) ? bj*128 : 0;
    int k1 = (MODE == 1) ? (bj+1)*128 : (bi+1)*128;

    extern __shared__ __align__(16) bf16 sm[];
    uint32_t smbase = (uint32_t)__cvta_generic_to_shared(sm);
    uint32_t AB = smbase;                 // 3 stages A
    uint32_t BBs = smbase + 3*ASTG_H*2;   // 3 stages B

    int tid  = threadIdx.x;
    int wid  = tid >> 5, lane = tid & 31;
    int gid  = lane >> 2, tig = lane & 3;
    int g    = lane >> 3, rsel = lane & 7;   // ldmatrix lane-group / row-in-group
    int wm   = (wid & 3) * 32;
    int wn   = (wid >> 2) * 64;
    int row0 = bi*128, col0 = bj*128;

    float c[2][8][4] = {};

    auto load_stage = [&](int s, int kb) {
        uint32_t Ad = AB + (s*ASTG_H)*2;
        #pragma unroll
        for (int h = 0; h < 2; h++) {        // A: 128 rows x 32 halves (64B) = 512 chunks
            int chunk = tid + 256*h;
            int r = chunk >> 2, c8 = (chunk & 3) * 8;
            uint32_t dst = Ad + (r*40 + c8)*2;
            const bf16* src = &Ab[(size_t)(row0 + r)*NN + kb + c8];
            asm volatile("cp.async.ca.shared.global [%0], [%1], 16;\n" :: "r"(dst), "l"(src));
        }
        uint32_t Bd = BBs + (s*BSTG)*2;
        if (MODE == 1) {                     // B: 128 n-rows x 32 halves
            #pragma unroll
            for (int h = 0; h < 2; h++) {
                int chunk = tid + 256*h;
                int r = chunk >> 2, c8 = (chunk & 3) * 8;
                uint32_t dst = Bd + (r*BSTR + c8)*2;
                const bf16* src = &Bb[(size_t)(col0 + r)*NN + kb + c8];
                asm volatile("cp.async.ca.shared.global [%0], [%1], 16;\n" :: "r"(dst), "l"(src));
            }
        } else {                             // B: 32 k-rows x 128 halves (256B)
            #pragma unroll
            for (int h = 0; h < 2; h++) {
                int chunk = tid + 256*h;
                int r = chunk >> 4, c8 = (chunk & 15) * 8;
                uint32_t dst = Bd + (r*BSTR + c8)*2;
                const bf16* src = &Bb[(size_t)(kb + r)*NN + col0 + c8];
                asm volatile("cp.async.ca.shared.global [%0], [%1], 16;\n" :: "r"(dst), "l"(src));
            }
        }
    };

    auto compute = [&](int s) {
        uint32_t Ac = AB + (s*ASTG_H)*2;
        uint32_t Bc = BBs + (s*BSTG)*2;
        #pragma unroll
        for (int kk = 0; kk < 32; kk += 16) {
            // A frags: 2 x ldmatrix.x4, quads (m0-7,k0-7),(m8-15,k0-7),(m0-7,k8-15),(m8-15,k8-15)
            uint32_t a[2][4];
            #pragma unroll
            for (int i = 0; i < 2; i++) {
                int row = wm + i*16 + (g & 1)*8 + rsel;
                int col = kk + (g >> 1)*8;
                uint32_t addr = Ac + (row*40 + col)*2;
                asm volatile("ldmatrix.sync.aligned.m8n8.x4.shared.b16 {%0,%1,%2,%3}, [%4];"
                             : "=r"(a[i][0]), "=r"(a[i][1]), "=r"(a[i][2]), "=r"(a[i][3])
                             : "r"(addr));
            }
            // B frags: 4 x ldmatrix.x4, each yields frags for n16
            uint32_t bfr[8][2];
            #pragma unroll
            for (int u = 0; u < 4; u++) {
                int n0 = wn + u*16;
                uint32_t r0, r1, r2, r3;
                if (MODE == 1) {             // [n][k]: quads (n0-7,k0-7),(n0-7,k8),(n8,k0-7),(n8,k8)
                    int n = n0 + (g >> 1)*8 + rsel;
                    int k = kk + (g & 1)*8;
                    uint32_t addr = Bc + (n*BSTR + k)*2;
                    asm volatile("ldmatrix.sync.aligned.m8n8.x4.shared.b16 {%0,%1,%2,%3}, [%4];"
                                 : "=r"(r0), "=r"(r1), "=r"(r2), "=r"(r3) : "r"(addr));
                } else {                     // [k][n] + trans
                    int k = kk + (g & 1)*8 + rsel;
                    int n = n0 + (g >> 1)*8;
                    uint32_t addr = Bc + (k*BSTR + n)*2;
                    asm volatile("ldmatrix.sync.aligned.m8n8.x4.trans.shared.b16 {%0,%1,%2,%3}, [%4];"
                                 : "=r"(r0), "=r"(r1), "=r"(r2), "=r"(r3) : "r"(addr));
                }
                bfr[2*u  ][0] = r0; bfr[2*u  ][1] = r1;
                bfr[2*u+1][0] = r2; bfr[2*u+1][1] = r3;
            }
            #pragma unroll
            for (int i = 0; i < 2; i++)
                #pragma unroll
                for (int j = 0; j < 8; j++) {
                    asm volatile(
                        "mma.sync.aligned.m16n8k16.row.col.f32.bf16.bf16.f32 "
                        "{%0,%1,%2,%3}, {%4,%5,%6,%7}, {%8,%9}, {%0,%1,%2,%3};"
                        : "+f"(c[i][j][0]), "+f"(c[i][j][1]),
                          "+f"(c[i][j][2]), "+f"(c[i][j][3])
                        : "r"(a[i][0]), "r"(a[i][1]), "r"(a[i][2]), "r"(a[i][3]),
                          "r"(bfr[j][0]), "r"(bfr[j][1]));
                }
        }
    };

    int nslab = (k1 - k0) >> 5;              // >= 4
    load_stage(0, k0);
    asm volatile("cp.async.commit_group;\n");
    load_stage(1, k0 + 32);
    asm volatile("cp.async.commit_group;\n");

    int sc = 0, sl = 2;
    for (int t = 0; t < nslab - 1; t++) {
        asm volatile("cp.async.wait_group 1;\n");
        __syncthreads();
        if (t + 2 < nslab) {
            load_stage(sl, k0 + (t+2)*32);
            asm volatile("cp.async.commit_group;\n");
            sl = (sl == 2) ? 0 : sl + 1;
        }
        compute(sc);
        sc = (sc == 2) ? 0 : sc + 1;
    }
    asm volatile("cp.async.wait_group 0;\n");
    __syncthreads();
    compute(sc);

    #pragma unroll
    for (int i = 0; i < 2; i++) {
        #pragma unroll
        for (int j = 0; j < 8; j++) {
            int gc = col0 + wn + j*8 + tig*2;
            #pragma unroll
            for (int h = 0; h < 2; h++) {
                int gr = row0 + wm + i*16 + gid + h*8;
                float vx = c[i][j][h*2], vy = c[i][j][h*2+1];
                if (MODE == 2) {
                    if (gc+0 > gr) vx = 0.f;
                    if (gc+1 > gr) vy = 0.f;
                }
                __nv_bfloat162 v = __floats2bfloat162_rn(vx, vy);
                *(__nv_bfloat162*)&Cb[(size_t)gr*NN + gc] = v;
            }
        }
    }
}

// ---------------------------------------------------------------------------
// Layer 4 (row 1023 only) + logits. P is bf16 now; accumulation in fp32.
// ---------------------------------------------------------------------------
__global__ void l4_q(const float* __restrict__ R, const int* __restrict__ tok,
                     const bf16* __restrict__ P, float* __restrict__ q) {
    int b = blockIdx.x;
    __shared__ float rsh[NN];
    __shared__ int   tsh[NN];
    for (int i = threadIdx.x; i < NN; i += blockDim.x) {
        rsh[i] = __bfloat162float(P[((size_t)b*NN + (NN-1))*NN + i]);
        tsh[i] = tok[b*NN + i];
    }
    __syncthreads();
    int d0 = threadIdx.x, d1 = d0 + 512, d2 = d0 + 1024;
    float a0 = 0.f, a1 = 0.f, a2 = 0.f;
    for (int m = 0; m < NN; m++) {
        float r = rsh[m];
        const float* Rt = R + (size_t)tsh[m]*DD;
        const float* Rp = R + (size_t)(VV + m)*DD;
        a0 += r * (Rt[d0] + Rp[d0]);
        a1 += r * (Rt[d1] + Rp[d1]);
        a2 += r * (Rt[d2] + Rp[d2]);
    }
    q[b*DD + d0] = a0; q[b*DD + d1] = a1; q[b*DD + d2] = a2;
}

__global__ void l4_u(const float* __restrict__ q, const int* __restrict__ tok,
                     float* __restrict__ u) {
    int b = blockIdx.x;
    for (int m = threadIdx.x; m < NN; m += blockDim.x) {
        int t = tok[b*NN + m];
        u[b*NN + m] = q[b*DD + t] + q[b*DD + VV + m];
    }
}

__global__ void l4_srow(const float* __restrict__ u, const bf16* __restrict__ P,
                        float* __restrict__ srow) {
    int b = blockIdx.y;
    __shared__ float ush[NN];
    for (int i = threadIdx.x; i < NN; i += 256) ush[i] = u[b*NN + i];
    __syncthreads();
    int row  = blockIdx.x * 8 + (threadIdx.x >> 5);
    int lane = threadIdx.x & 31;
    const bf16* Prow = P + ((size_t)b*NN + row)*NN;
    float acc = 0.f;
    for (int k = lane; k < NN; k += 32) acc += ush[k] * __bfloat162float(Prow[k]);
    for (int o = 16; o; o >>= 1) acc += __shfl_down_sync(0xffffffffu, acc, o);
    if (lane == 0) srow[b*NN + row] = acc;
}

__global__ void l4_softmax(const float* __restrict__ s, float* __restrict__ a) {
    int b = blockIdx.x;
    __shared__ float red[256];
    float mx = -1e30f;
    for (int m = threadIdx.x; m < NN; m += 256) mx = fmaxf(mx, s[b*NN + m]);
    red[threadIdx.x] = mx; __syncthreads();
    for (int st = 128; st > 0; st >>= 1) {
        if (threadIdx.x < st) red[threadIdx.x] = fmaxf(red[threadIdx.x], red[threadIdx.x+st]);
        __syncthreads();
    }
    mx = red[0]; __syncthreads();
    float sum = 0.f;
    for (int m = threadIdx.x; m < NN; m += 256) {
        float e = __expf(s[b*NN + m] - mx);
        a[b*NN + m] = e; sum += e;
    }
    red[threadIdx.x] = sum; __syncthreads();
    for (int st = 128; st > 0; st >>= 1) {
        if (threadIdx.x < st) red[threadIdx.x] += red[threadIdx.x+st];
        __syncthreads();
    }
    float inv = 1.f / red[0];
    for (int m = threadIdx.x; m < NN; m += 256) a[b*NN + m] *= inv;
}

__global__ void l4_p(const float* __restrict__ a, const bf16* __restrict__ P,
                     float* __restrict__ p) {
    int b = blockIdx.y;
    int k = blockIdx.x * 256 + threadIdx.x;
    __shared__ float ash[NN];
    for (int i = threadIdx.x; i < NN; i += 256) ash[i] = a[b*NN + i];
    __syncthreads();
    float acc = 0.f;
    for (int m = 0; m < NN; m++) acc += ash[m] * __bfloat162float(P[((size_t)b*NN + m)*NN + k]);
    p[b*NN + k] = acc;
}

__global__ void l4_c(const int* __restrict__ tok, const float* __restrict__ p,
                     float* __restrict__ c) {
    int b = blockIdx.x;
    __shared__ float psh[NN];
    __shared__ int   tsh[NN];
    for (int i = threadIdx.x; i < NN; i += blockDim.x) {
        psh[i] = p[b*NN + i];
        tsh[i] = tok[b*NN + i];
    }
    __syncthreads();
    int w = threadIdx.x;  // blockDim.x == 512 == VV
    float acc = 0.f;
    for (int m = 0; m < NN; m++)
        if (tsh[m] == w) acc += psh[m];
    c[b*VV + w] = acc;
}

__global__ void l4_logits(const float* __restrict__ c, const float* __restrict__ p,
                          const float* __restrict__ U, float* __restrict__ out) {
    int b = blockIdx.y;
    __shared__ float hsh[DD];
    for (int i = threadIdx.x; i < VV; i += 256) hsh[i]      = c[b*VV + i];
    for (int i = threadIdx.x; i < NN; i += 256) hsh[VV + i] = p[b*NN + i];
    __syncthreads();
    int wid = threadIdx.x >> 5, lane = threadIdx.x & 31;
    int v = blockIdx.x * 8 + wid;
    const float* Ur = U + (size_t)v*DD;
    float acc = 0.f;
    for (int j = lane; j < DD; j += 32) acc += hsh[j] * Ur[j];
    for (int o = 16; o; o >>= 1) acc += __shfl_down_sync(0xffffffffu, acc, o);
    if (lane == 0) out[b*VV + v] = acc;
}

// ---------------------------------------------------------------------------
extern "C" void kernel_launch(void* const* d_in, const int* in_sizes, int n_in,
                              void* d_out, int out_size) {
    const int*   tok = (const int*)  d_in[0];
    const float* R   = (const float*)d_in[1];
    const float* U   = (const float*)d_in[2];
    float*       out = (float*)d_out;

    bf16 *S, *P, *T, *A, *PN;
    float *q, *u, *sr, *a, *p, *c;
    cudaGetSymbolAddress((void**)&S,  g_S);
    cudaGetSymbolAddress((void**)&P,  g_P);
    cudaGetSymbolAddress((void**)&T,  g_T);
    cudaGetSymbolAddress((void**)&A,  g_A);
    cudaGetSymbolAddress((void**)&PN, g_PN);
    cudaGetSymbolAddress((void**)&q,  g_q);
    cudaGetSymbolAddress((void**)&u,  g_u);
    cudaGetSymbolAddress((void**)&sr, g_sr);
    cudaGetSymbolAddress((void**)&a,  g_a);
    cudaGetSymbolAddress((void**)&p,  g_p);
    cudaGetSymbolAddress((void**)&c,  g_c);

    // dynamic smem: 3 stages of (A + B), in bytes (halves * 2)
    const int SM0 = (3*ASTG_H + 3*BC<0>::STG) * 2;   // 56832
    const int SM1 = (3*ASTG_H + 3*BC<1>::STG) * 2;   // 61440
    cudaFuncSetAttribute(gemm_bf16<0>, cudaFuncAttributeMaxDynamicSharedMemorySize, SM0);
    cudaFuncSetAttribute(gemm_bf16<1>, cudaFuncAttributeMaxDynamicSharedMemorySize, SM1);
    cudaFuncSetAttribute(gemm_bf16<2>, cudaFuncAttributeMaxDynamicSharedMemorySize, SM0);

    dim3 gRow(NN, BB), gT(8, 8, BB);
    const size_t RS = (size_t)DD*DD;

    // Layer 1 fused: P2 = softmax(S1), bf16
    gather_softmax1<<<gRow, 256>>>(R + 0*RS, tok, P);

    // Layer 2: scores = P*S2*P^T ; A2 = softmax ; P3 = A2*P
    gather_S      <<<gRow, 256>>>(R + 1*RS, tok, S);
    gemm_bf16<0>  <<<gT, 256, SM0>>>(P, S, T);
    gemm_bf16<1>  <<<gT, 256, SM1>>>(T, P, A);
    softmax_causal<<<gRow, 256>>>(A, A);
    gemm_bf16<2>  <<<gT, 256, SM0>>>(A, P, PN);

    // Layer 3: same with P3 (in PN) -> P4 (into P)
    gather_S      <<<gRow, 256>>>(R + 2*RS, tok, S);
    gemm_bf16<0>  <<<gT, 256, SM0>>>(PN, S, T);
    gemm_bf16<1>  <<<gT, 256, SM1>>>(T, PN, A);
    softmax_causal<<<gRow, 256>>>(A, A);
    gemm_bf16<2>  <<<gT, 256, SM0>>>(A, PN, P);

    // Layer 4 (row 1023 only) + logits
    l4_q      <<<BB, 512>>>(R + 3*RS, tok, P, q);
    l4_u      <<<BB, 256>>>(q, tok, u);
    l4_srow   <<<dim3(128, BB), 256>>>(u, P, sr);
    l4_softmax<<<BB, 256>>>(sr, a);
    l4_p      <<<dim3(4, BB), 256>>>(a, P, p);
    l4_c      <<<BB, 512>>>(tok, p, c);
    l4_logits <<<dim3(64, BB), 256>>>(c, p, U, out);
}

// round 8
// speedup vs baseline: 3.7925x; 1.1462x over previous
#include <cuda_runtime.h>
#include <cuda_bf16.h>
#include <cstdint>

// Problem constants
#define BB 32
#define NN 1024
#define VV 512
#define DD 1536

typedef __nv_bfloat16 bf16;

// Scratch buffers (allocation-free rule: __device__ globals). Big tensors bf16.
__device__ bf16  g_S [(size_t)BB*NN*NN];
__device__ bf16  g_P [(size_t)BB*NN*NN];
__device__ bf16  g_T [(size_t)BB*NN*NN];
__device__ bf16  g_A [(size_t)BB*NN*NN];
__device__ bf16  g_PN[(size_t)BB*NN*NN];
__device__ float g_u [BB*NN];
__device__ float g_sr[BB*NN];
__device__ float g_a [BB*NN];
__device__ float g_p [BB*NN];
__device__ float g_c [BB*VV];

// Block-wide reductions over 8 warps (256 threads), value broadcast to all.
__device__ __forceinline__ float blk_max(float v, float* rs, int t) {
    #pragma unroll
    for (int o = 16; o; o >>= 1) v = fmaxf(v, __shfl_xor_sync(0xffffffffu, v, o));
    if ((t & 31) == 0) rs[t >> 5] = v;
    __syncthreads();
    float r = rs[0];
    #pragma unroll
    for (int w = 1; w < 8; w++) r = fmaxf(r, rs[w]);
    return r;
}
__device__ __forceinline__ float blk_sum(float v, float* rs, int t) {
    #pragma unroll
    for (int o = 16; o; o >>= 1) v += __shfl_xor_sync(0xffffffffu, v, o);
    if ((t & 31) == 0) rs[t >> 5] = v;
    __syncthreads();
    float r = rs[0];
    #pragma unroll
    for (int w = 1; w < 8; w++) r += rs[w];
    return r;
}

// ---------------------------------------------------------------------------
// Fused layer 1: scores gathered from Wsh, register softmax, bf16x4 writes.
// ---------------------------------------------------------------------------
__global__ void __launch_bounds__(256)
gather_softmax1(const float* __restrict__ R, const int* __restrict__ tok,
                bf16* __restrict__ P) {
    int b = blockIdx.y, m = blockIdx.x;
    __shared__ float Wsh[DD];
    __shared__ int   tsh[NN];
    __shared__ float rs[8];
    const int* tb = tok + b*NN;
    int t = threadIdx.x;
    int tm = tb[m];
    for (int d = t; d < DD; d += 256)
        Wsh[d] = R[(size_t)tm*DD + d] + R[(size_t)(VV + m)*DD + d];
    for (int i = t; i < NN; i += 256) tsh[i] = tb[i];
    __syncthreads();

    int i0 = t*4;
    float v[4];
    #pragma unroll
    for (int k = 0; k < 4; k++)
        v[k] = (i0+k <= m) ? (Wsh[tsh[i0+k]] + Wsh[VV + i0+k]) : -1e30f;
    float mx = fmaxf(fmaxf(v[0], v[1]), fmaxf(v[2], v[3]));
    mx = blk_max(mx, rs, t);
    __syncthreads();
    float e[4];
    #pragma unroll
    for (int k = 0; k < 4; k++)
        e[k] = (i0+k <= m) ? __expf(v[k] - mx) : 0.f;
    float sum = blk_sum(e[0]+e[1]+e[2]+e[3], rs, t);
    float inv = 1.f / sum;
    bf16* arow = P + ((size_t)b*NN + m)*NN;
    uint2 out;
    __nv_bfloat162 o0 = __floats2bfloat162_rn(e[0]*inv, e[1]*inv);
    __nv_bfloat162 o1 = __floats2bfloat162_rn(e[2]*inv, e[3]*inv);
    out.x = *(uint32_t*)&o0; out.y = *(uint32_t*)&o1;
    *(uint2*)(arow + i0) = out;
}

// ---------------------------------------------------------------------------
// S_k gather: 4 rows per block (token list amortized), 8B bf16x4 stores.
// ---------------------------------------------------------------------------
__global__ void __launch_bounds__(256)
gather_S(const float* __restrict__ R, const int* __restrict__ tok,
         bf16* __restrict__ S) {
    int b = blockIdx.y;
    __shared__ float Wsh[DD];
    __shared__ int   tsh[NN];
    const int* tb = tok + b*NN;
    int t = threadIdx.x;
    for (int i = t; i < NN; i += 256) tsh[i] = tb[i];
    int i0 = t*4;
    #pragma unroll
    for (int r = 0; r < 4; r++) {
        int m = blockIdx.x*4 + r;
        __syncthreads();
        int tm = tb[m];
        for (int d = t; d < DD; d += 256)
            Wsh[d] = R[(size_t)tm*DD + d] + R[(size_t)(VV + m)*DD + d];
        __syncthreads();
        float4 wp = *(const float4*)&Wsh[VV + i0];
        float v0 = Wsh[tsh[i0+0]] + wp.x;
        float v1 = Wsh[tsh[i0+1]] + wp.y;
        float v2 = Wsh[tsh[i0+2]] + wp.z;
        float v3 = Wsh[tsh[i0+3]] + wp.w;
        __nv_bfloat162 o0 = __floats2bfloat162_rn(v0, v1);
        __nv_bfloat162 o1 = __floats2bfloat162_rn(v2, v3);
        uint2 out; out.x = *(uint32_t*)&o0; out.y = *(uint32_t*)&o1;
        *(uint2*)(S + ((size_t)b*NN + m)*NN + i0) = out;
    }
}

// ---------------------------------------------------------------------------
// Causal row softmax: register-resident, one read / one exp / one 8B write.
// ---------------------------------------------------------------------------
__global__ void __launch_bounds__(256)
softmax_causal(const bf16* __restrict__ S, bf16* __restrict__ A) {
    int b = blockIdx.y, n = blockIdx.x;
    __shared__ float rs[8];
    const bf16* srow = S + ((size_t)b*NN + n)*NN;
    bf16*       arow = A + ((size_t)b*NN + n)*NN;
    int t = threadIdx.x;
    int i0 = t*4;
    uint2 raw = *(const uint2*)(srow + i0);
    float2 f0 = __bfloat1622float2(*(__nv_bfloat162*)&raw.x);
    float2 f1 = __bfloat1622float2(*(__nv_bfloat162*)&raw.y);
    float v[4] = { (i0+0 <= n) ? f0.x : -1e30f, (i0+1 <= n) ? f0.y : -1e30f,
                   (i0+2 <= n) ? f1.x : -1e30f, (i0+3 <= n) ? f1.y : -1e30f };
    float mx = fmaxf(fmaxf(v[0], v[1]), fmaxf(v[2], v[3]));
    mx = blk_max(mx, rs, t);
    __syncthreads();
    float e[4];
    #pragma unroll
    for (int k = 0; k < 4; k++)
        e[k] = (i0+k <= n) ? __expf(v[k] - mx) : 0.f;
    float sum = blk_sum(e[0]+e[1]+e[2]+e[3], rs, t);
    float inv = 1.f / sum;
    __nv_bfloat162 o0 = __floats2bfloat162_rn(e[0]*inv, e[1]*inv);
    __nv_bfloat162 o1 = __floats2bfloat162_rn(e[2]*inv, e[3]*inv);
    uint2 out; out.x = *(uint32_t*)&o0; out.y = *(uint32_t*)&o1;
    *(uint2*)(arow + i0) = out;
}

// ---------------------------------------------------------------------------
// Batched 1024^3 bf16 GEMM: mma.sync m16n8k16, ldmatrix, 3-stage cp.async.
// (unchanged from round 7)
// ---------------------------------------------------------------------------
#define ASTG_H (128*40)
template<int MODE>
struct BC { static constexpr int STR = 136, STG = 32*136; };
template<> struct BC<1> { static constexpr int STR = 40, STG = 128*40; };

template<int MODE>
__global__ void __launch_bounds__(256)
gemm_bf16(const bf16* __restrict__ Ag, const bf16* __restrict__ Bg,
          bf16* __restrict__ Cg) {
    constexpr int BSTR = BC<MODE>::STR;
    constexpr int BSTG = BC<MODE>::STG;
    int bi = blockIdx.y, bj = blockIdx.x, b = blockIdx.z;
    if (MODE != 0 && bj > bi) return;
    const bf16* Ab = Ag + (size_t)b*NN*NN;
    const bf16* Bb = Bg + (size_t)b*NN*NN;
    bf16*       Cb = Cg + (size_t)b*NN*NN;
    int k0 = (MODE == 2) ? bj*128 : 0;
    int k1 = (MODE == 1) ? (bj+1)*128 : (bi+1)*128;

    extern __shared__ __align__(16) bf16 sm[];
    uint32_t smbase = (uint32_t)__cvta_generic_to_shared(sm);
    uint32_t AB = smbase;
    uint32_t BBs = smbase + 3*ASTG_H*2;

    int tid  = threadIdx.x;
    int wid  = tid >> 5, lane = tid & 31;
    int gid  = lane >> 2, tig = lane & 3;
    int g    = lane >> 3, rsel = lane & 7;
    int wm   = (wid & 3) * 32;
    int wn   = (wid >> 2) * 64;
    int row0 = bi*128, col0 = bj*128;

    float c[2][8][4] = {};

    auto load_stage = [&](int s, int kb) {
        uint32_t Ad = AB + (s*ASTG_H)*2;
        #pragma unroll
        for (int h = 0; h < 2; h++) {
            int chunk = tid + 256*h;
            int r = chunk >> 2, c8 = (chunk & 3) * 8;
            uint32_t dst = Ad + (r*40 + c8)*2;
            const bf16* src = &Ab[(size_t)(row0 + r)*NN + kb + c8];
            asm volatile("cp.async.ca.shared.global [%0], [%1], 16;\n" :: "r"(dst), "l"(src));
        }
        uint32_t Bd = BBs + (s*BSTG)*2;
        if (MODE == 1) {
            #pragma unroll
            for (int h = 0; h < 2; h++) {
                int chunk = tid + 256*h;
                int r = chunk >> 2, c8 = (chunk & 3) * 8;
                uint32_t dst = Bd + (r*BSTR + c8)*2;
                const bf16* src = &Bb[(size_t)(col0 + r)*NN + kb + c8];
                asm volatile("cp.async.ca.shared.global [%0], [%1], 16;\n" :: "r"(dst), "l"(src));
            }
        } else {
            #pragma unroll
            for (int h = 0; h < 2; h++) {
                int chunk = tid + 256*h;
                int r = chunk >> 4, c8 = (chunk & 15) * 8;
                uint32_t dst = Bd + (r*BSTR + c8)*2;
                const bf16* src = &Bb[(size_t)(kb + r)*NN + col0 + c8];
                asm volatile("cp.async.ca.shared.global [%0], [%1], 16;\n" :: "r"(dst), "l"(src));
            }
        }
    };

    auto compute = [&](int s) {
        uint32_t Ac = AB + (s*ASTG_H)*2;
        uint32_t Bc = BBs + (s*BSTG)*2;
        #pragma unroll
        for (int kk = 0; kk < 32; kk += 16) {
            uint32_t a[2][4];
            #pragma unroll
            for (int i = 0; i < 2; i++) {
                int row = wm + i*16 + (g & 1)*8 + rsel;
                int col = kk + (g >> 1)*8;
                uint32_t addr = Ac + (row*40 + col)*2;
                asm volatile("ldmatrix.sync.aligned.m8n8.x4.shared.b16 {%0,%1,%2,%3}, [%4];"
                             : "=r"(a[i][0]), "=r"(a[i][1]), "=r"(a[i][2]), "=r"(a[i][3])
                             : "r"(addr));
            }
            uint32_t bfr[8][2];
            #pragma unroll
            for (int u = 0; u < 4; u++) {
                int n0 = wn + u*16;
                uint32_t r0, r1, r2, r3;
                if (MODE == 1) {
                    int n = n0 + (g >> 1)*8 + rsel;
                    int k = kk + (g & 1)*8;
                    uint32_t addr = Bc + (n*BSTR + k)*2;
                    asm volatile("ldmatrix.sync.aligned.m8n8.x4.shared.b16 {%0,%1,%2,%3}, [%4];"
                                 : "=r"(r0), "=r"(r1), "=r"(r2), "=r"(r3) : "r"(addr));
                } else {
                    int k = kk + (g & 1)*8 + rsel;
                    int n = n0 + (g >> 1)*8;
                    uint32_t addr = Bc + (k*BSTR + n)*2;
                    asm volatile("ldmatrix.sync.aligned.m8n8.x4.trans.shared.b16 {%0,%1,%2,%3}, [%4];"
                                 : "=r"(r0), "=r"(r1), "=r"(r2), "=r"(r3) : "r"(addr));
                }
                bfr[2*u  ][0] = r0; bfr[2*u  ][1] = r1;
                bfr[2*u+1][0] = r2; bfr[2*u+1][1] = r3;
            }
            #pragma unroll
            for (int i = 0; i < 2; i++)
                #pragma unroll
                for (int j = 0; j < 8; j++) {
                    asm volatile(
                        "mma.sync.aligned.m16n8k16.row.col.f32.bf16.bf16.f32 "
                        "{%0,%1,%2,%3}, {%4,%5,%6,%7}, {%8,%9}, {%0,%1,%2,%3};"
                        : "+f"(c[i][j][0]), "+f"(c[i][j][1]),
                          "+f"(c[i][j][2]), "+f"(c[i][j][3])
                        : "r"(a[i][0]), "r"(a[i][1]), "r"(a[i][2]), "r"(a[i][3]),
                          "r"(bfr[j][0]), "r"(bfr[j][1]));
                }
        }
    };

    int nslab = (k1 - k0) >> 5;
    load_stage(0, k0);
    asm volatile("cp.async.commit_group;\n");
    load_stage(1, k0 + 32);
    asm volatile("cp.async.commit_group;\n");

    int sc = 0, sl = 2;
    for (int t = 0; t < nslab - 1; t++) {
        asm volatile("cp.async.wait_group 1;\n");
        __syncthreads();
        if (t + 2 < nslab) {
            load_stage(sl, k0 + (t+2)*32);
            asm volatile("cp.async.commit_group;\n");
            sl = (sl == 2) ? 0 : sl + 1;
        }
        compute(sc);
        sc = (sc == 2) ? 0 : sc + 1;
    }
    asm volatile("cp.async.wait_group 0;\n");
    __syncthreads();
    compute(sc);

    #pragma unroll
    for (int i = 0; i < 2; i++) {
        #pragma unroll
        for (int j = 0; j < 8; j++) {
            int gc = col0 + wn + j*8 + tig*2;
            #pragma unroll
            for (int h = 0; h < 2; h++) {
                int gr = row0 + wm + i*16 + gid + h*8;
                float vx = c[i][j][h*2], vy = c[i][j][h*2+1];
                if (MODE == 2) {
                    if (gc+0 > gr) vx = 0.f;
                    if (gc+1 > gr) vy = 0.f;
                }
                __nv_bfloat162 v = __floats2bfloat162_rn(vx, vy);
                *(__nv_bfloat162*)&Cb[(size_t)gr*NN + gc] = v;
            }
        }
    }
}

// ---------------------------------------------------------------------------
// Layer 4 (row 1023 only) + logits
// ---------------------------------------------------------------------------
__global__ void l4_qu(const float* __restrict__ R, const int* __restrict__ tok,
                      const bf16* __restrict__ P, float* __restrict__ u) {
    int b = blockIdx.x;
    __shared__ float rsh[NN];
    __shared__ int   tsh[NN];
    __shared__ float qsh[DD];
    for (int i = threadIdx.x; i < NN; i += blockDim.x) {
        rsh[i] = __bfloat162float(P[((size_t)b*NN + (NN-1))*NN + i]);
        tsh[i] = tok[b*NN + i];
    }
    __syncthreads();
    int d0 = threadIdx.x, d1 = d0 + 512, d2 = d0 + 1024;
    float a0 = 0.f, a1 = 0.f, a2 = 0.f;
    for (int m = 0; m < NN; m++) {
        float r = rsh[m];
        const float* Rt = R + (size_t)tsh[m]*DD;
        const float* Rp = R + (size_t)(VV + m)*DD;
        a0 += r * (Rt[d0] + Rp[d0]);
        a1 += r * (Rt[d1] + Rp[d1]);
        a2 += r * (Rt[d2] + Rp[d2]);
    }
    qsh[d0] = a0; qsh[d1] = a1; qsh[d2] = a2;
    __syncthreads();
    for (int m = threadIdx.x; m < NN; m += blockDim.x)
        u[b*NN + m] = qsh[tsh[m]] + qsh[VV + m];
}

__global__ void l4_srow(const float* __restrict__ u, const bf16* __restrict__ P,
                        float* __restrict__ srow) {
    int b = blockIdx.y;
    __shared__ float ush[NN];
    for (int i = threadIdx.x; i < NN; i += 256) ush[i] = u[b*NN + i];
    __syncthreads();
    int row  = blockIdx.x * 8 + (threadIdx.x >> 5);
    int lane = threadIdx.x & 31;
    const bf16* Prow = P + ((size_t)b*NN + row)*NN;
    float acc = 0.f;
    for (int k = lane; k < NN; k += 32) acc += ush[k] * __bfloat162float(Prow[k]);
    for (int o = 16; o; o >>= 1) acc += __shfl_down_sync(0xffffffffu, acc, o);
    if (lane == 0) srow[b*NN + row] = acc;
}

__global__ void l4_softmax(const float* __restrict__ s, float* __restrict__ a) {
    int b = blockIdx.x;
    __shared__ float rs[8];
    int t = threadIdx.x;
    int i0 = t*4;
    float4 v4 = *(const float4*)&s[b*NN + i0];
    float v[4] = { v4.x, v4.y, v4.z, v4.w };
    float mx = fmaxf(fmaxf(v[0], v[1]), fmaxf(v[2], v[3]));
    mx = blk_max(mx, rs, t);
    __syncthreads();
    float e[4];
    #pragma unroll
    for (int k = 0; k < 4; k++) e[k] = __expf(v[k] - mx);
    float sum = blk_sum(e[0]+e[1]+e[2]+e[3], rs, t);
    float inv = 1.f / sum;
    float4 o = make_float4(e[0]*inv, e[1]*inv, e[2]*inv, e[3]*inv);
    *(float4*)&a[b*NN + i0] = o;
}

__global__ void l4_p(const float* __restrict__ a, const bf16* __restrict__ P,
                     float* __restrict__ p) {
    int b = blockIdx.y;
    int k = blockIdx.x * 256 + threadIdx.x;
    __shared__ float ash[NN];
    for (int i = threadIdx.x; i < NN; i += 256) ash[i] = a[b*NN + i];
    __syncthreads();
    float acc = 0.f;
    for (int m = 0; m < NN; m++) acc += ash[m] * __bfloat162float(P[((size_t)b*NN + m)*NN + k]);
    p[b*NN + k] = acc;
}

__global__ void l4_c(const int* __restrict__ tok, const float* __restrict__ p,
                     float* __restrict__ c) {
    int b = blockIdx.x;
    __shared__ float psh[NN];
    __shared__ int   tsh[NN];
    for (int i = threadIdx.x; i < NN; i += blockDim.x) {
        psh[i] = p[b*NN + i];
        tsh[i] = tok[b*NN + i];
    }
    __syncthreads();
    int w = threadIdx.x;  // blockDim.x == 512 == VV
    float acc = 0.f;
    for (int m = 0; m < NN; m++)
        if (tsh[m] == w) acc += psh[m];
    c[b*VV + w] = acc;
}

__global__ void l4_logits(const float* __restrict__ c, const float* __restrict__ p,
                          const float* __restrict__ U, float* __restrict__ out) {
    int b = blockIdx.y;
    __shared__ float hsh[DD];
    for (int i = threadIdx.x; i < VV; i += 256) hsh[i]      = c[b*VV + i];
    for (int i = threadIdx.x; i < NN; i += 256) hsh[VV + i] = p[b*NN + i];
    __syncthreads();
    int wid = threadIdx.x >> 5, lane = threadIdx.x & 31;
    int v = blockIdx.x * 8 + wid;
    const float* Ur = U + (size_t)v*DD;
    float acc = 0.f;
    for (int j = lane; j < DD; j += 32) acc += hsh[j] * Ur[j];
    for (int o = 16; o; o >>= 1) acc += __shfl_down_sync(0xffffffffu, acc, o);
    if (lane == 0) out[b*VV + v] = acc;
}

// ---------------------------------------------------------------------------
extern "C" void kernel_launch(void* const* d_in, const int* in_sizes, int n_in,
                              void* d_out, int out_size) {
    const int*   tok = (const int*)  d_in[0];
    const float* R   = (const float*)d_in[1];
    const float* U   = (const float*)d_in[2];
    float*       out = (float*)d_out;

    bf16 *S, *P, *T, *A, *PN;
    float *u, *sr, *a, *p, *c;
    cudaGetSymbolAddress((void**)&S,  g_S);
    cudaGetSymbolAddress((void**)&P,  g_P);
    cudaGetSymbolAddress((void**)&T,  g_T);
    cudaGetSymbolAddress((void**)&A,  g_A);
    cudaGetSymbolAddress((void**)&PN, g_PN);
    cudaGetSymbolAddress((void**)&u,  g_u);
    cudaGetSymbolAddress((void**)&sr, g_sr);
    cudaGetSymbolAddress((void**)&a,  g_a);
    cudaGetSymbolAddress((void**)&p,  g_p);
    cudaGetSymbolAddress((void**)&c,  g_c);

    const int SM0 = (3*ASTG_H + 3*BC<0>::STG) * 2;
    const int SM1 = (3*ASTG_H + 3*BC<1>::STG) * 2;
    cudaFuncSetAttribute(gemm_bf16<0>, cudaFuncAttributeMaxDynamicSharedMemorySize, SM0);
    cudaFuncSetAttribute(gemm_bf16<1>, cudaFuncAttributeMaxDynamicSharedMemorySize, SM1);
    cudaFuncSetAttribute(gemm_bf16<2>, cudaFuncAttributeMaxDynamicSharedMemorySize, SM0);

    dim3 gRow(NN, BB), gRow4(NN/4, BB), gT(8, 8, BB);
    const size_t RS = (size_t)DD*DD;

    // Layer 1 fused: P2 = softmax(S1), bf16
    gather_softmax1<<<gRow, 256>>>(R + 0*RS, tok, P);

    // Layer 2: scores = P*S2*P^T ; A2 = softmax ; P3 = A2*P
    gather_S      <<<gRow4, 256>>>(R + 1*RS, tok, S);
    gemm_bf16<0>  <<<gT, 256, SM0>>>(P, S, T);
    gemm_bf16<1>  <<<gT, 256, SM1>>>(T, P, A);
    softmax_causal<<<gRow, 256>>>(A, A);
    gemm_bf16<2>  <<<gT, 256, SM0>>>(A, P, PN);

    // Layer 3: same with P3 (in PN) -> P4 (into P)
    gather_S      <<<gRow4, 256>>>(R + 2*RS, tok, S);
    gemm_bf16<0>  <<<gT, 256, SM0>>>(PN, S, T);
    gemm_bf16<1>  <<<gT, 256, SM1>>>(T, PN, A);
    softmax_causal<<<gRow, 256>>>(A, A);
    gemm_bf16<2>  <<<gT, 256, SM0>>>(A, PN, P);

    // Layer 4 (row 1023 only) + logits
    l4_qu     <<<BB, 512>>>(R + 3*RS, tok, P, u);
    l4_srow   <<<dim3(128, BB), 256>>>(u, P, sr);
    l4_softmax<<<BB, 256>>>(sr, a);
    l4_p      <<<dim3(4, BB), 256>>>(a, P, p);
    l4_c      <<<BB, 512>>>(tok, p, c);
    l4_logits <<<dim3(64, BB), 256>>>(c, p, U, out);
}

// round 9
// speedup vs baseline: 4.9388x; 1.3022x over previous
#include <cuda_runtime.h>
#include <cuda_bf16.h>
#include <cstdint>

// Problem constants
#define BB 32
#define NN 1024
#define VV 512
#define DD 1536

typedef __nv_bfloat16 bf16;

// Scratch buffers (allocation-free rule: __device__ globals). Big tensors bf16.
__device__ bf16  g_Rb[(size_t)4*DD*DD];   // bf16 copy of R (all layers)
__device__ bf16  g_S [(size_t)BB*NN*NN];
__device__ bf16  g_P [(size_t)BB*NN*NN];
__device__ bf16  g_T [(size_t)BB*NN*NN];
__device__ bf16  g_A [(size_t)BB*NN*NN];
__device__ bf16  g_PN[(size_t)BB*NN*NN];
__device__ float g_qp[(size_t)BB*32*DD];
__device__ float g_u [BB*NN];
__device__ float g_sr[BB*NN];
__device__ float g_a [BB*NN];
__device__ float g_p [BB*NN];
__device__ float g_c [BB*VV];

__device__ __forceinline__ float2 bf2f(uint32_t u) {
    return __bfloat1622float2(*(__nv_bfloat162*)&u);
}

// Block-wide reductions over 8 warps (256 threads), value broadcast to all.
__device__ __forceinline__ float blk_max(float v, float* rs, int t) {
    #pragma unroll
    for (int o = 16; o; o >>= 1) v = fmaxf(v, __shfl_xor_sync(0xffffffffu, v, o));
    if ((t & 31) == 0) rs[t >> 5] = v;
    __syncthreads();
    float r = rs[0];
    #pragma unroll
    for (int w = 1; w < 8; w++) r = fmaxf(r, rs[w]);
    return r;
}
__device__ __forceinline__ float blk_sum(float v, float* rs, int t) {
    #pragma unroll
    for (int o = 16; o; o >>= 1) v += __shfl_xor_sync(0xffffffffu, v, o);
    if ((t & 31) == 0) rs[t >> 5] = v;
    __syncthreads();
    float r = rs[0];
    #pragma unroll
    for (int w = 1; w < 8; w++) r += rs[w];
    return r;
}

// ---------------------------------------------------------------------------
// R -> bf16 conversion (once per call; 9.4M elements)
// ---------------------------------------------------------------------------
__global__ void r_to_bf16(const float* __restrict__ R, bf16* __restrict__ Rb) {
    size_t i = ((size_t)blockIdx.x * 256 + threadIdx.x) * 4;
    float4 v = *(const float4*)(R + i);
    __nv_bfloat162 o0 = __floats2bfloat162_rn(v.x, v.y);
    __nv_bfloat162 o1 = __floats2bfloat162_rn(v.z, v.w);
    uint2 out; out.x = *(uint32_t*)&o0; out.y = *(uint32_t*)&o1;
    *(uint2*)(Rb + i) = out;
}

// ---------------------------------------------------------------------------
// Fused layer 1: scores gathered from Wsh (bf16 R), register softmax.
// ---------------------------------------------------------------------------
__global__ void __launch_bounds__(256)
gather_softmax1(const bf16* __restrict__ Rb, const int* __restrict__ tok,
                bf16* __restrict__ P) {
    int b = blockIdx.y, m = blockIdx.x;
    __shared__ float Wsh[DD];
    __shared__ int   tsh[NN];
    __shared__ float rs[8];
    const int* tb = tok + b*NN;
    int t = threadIdx.x;
    int tm = tb[m];
    const bf16* r0 = Rb + (size_t)tm*DD;
    const bf16* r1 = Rb + (size_t)(VV + m)*DD;
    for (int d4 = t*4; d4 < DD; d4 += 1024) {
        uint2 u0 = *(const uint2*)(r0 + d4);
        uint2 u1 = *(const uint2*)(r1 + d4);
        float2 a0 = bf2f(u0.x), a1 = bf2f(u0.y);
        float2 b0 = bf2f(u1.x), b1 = bf2f(u1.y);
        *(float4*)&Wsh[d4] = make_float4(a0.x+b0.x, a0.y+b0.y, a1.x+b1.x, a1.y+b1.y);
    }
    for (int i = t; i < NN; i += 256) tsh[i] = tb[i];
    __syncthreads();

    int i0 = t*4;
    float v[4];
    #pragma unroll
    for (int k = 0; k < 4; k++)
        v[k] = (i0+k <= m) ? (Wsh[tsh[i0+k]] + Wsh[VV + i0+k]) : -1e30f;
    float mx = fmaxf(fmaxf(v[0], v[1]), fmaxf(v[2], v[3]));
    mx = blk_max(mx, rs, t);
    __syncthreads();
    float e[4];
    #pragma unroll
    for (int k = 0; k < 4; k++)
        e[k] = (i0+k <= m) ? __expf(v[k] - mx) : 0.f;
    float sum = blk_sum(e[0]+e[1]+e[2]+e[3], rs, t);
    float inv = 1.f / sum;
    bf16* arow = P + ((size_t)b*NN + m)*NN;
    __nv_bfloat162 o0 = __floats2bfloat162_rn(e[0]*inv, e[1]*inv);
    __nv_bfloat162 o1 = __floats2bfloat162_rn(e[2]*inv, e[3]*inv);
    uint2 out; out.x = *(uint32_t*)&o0; out.y = *(uint32_t*)&o1;
    *(uint2*)(arow + i0) = out;
}

// ---------------------------------------------------------------------------
// S_k gather (bf16 R): 4 rows per block, 8B vector loads/stores.
// ---------------------------------------------------------------------------
__global__ void __launch_bounds__(256)
gather_S(const bf16* __restrict__ Rb, const int* __restrict__ tok,
         bf16* __restrict__ S) {
    int b = blockIdx.y;
    __shared__ float Wsh[DD];
    __shared__ int   tsh[NN];
    const int* tb = tok + b*NN;
    int t = threadIdx.x;
    for (int i = t; i < NN; i += 256) tsh[i] = tb[i];
    int i0 = t*4;
    #pragma unroll
    for (int r = 0; r < 4; r++) {
        int m = blockIdx.x*4 + r;
        __syncthreads();
        int tm = tb[m];
        const bf16* r0 = Rb + (size_t)tm*DD;
        const bf16* r1 = Rb + (size_t)(VV + m)*DD;
        for (int d4 = t*4; d4 < DD; d4 += 1024) {
            uint2 u0 = *(const uint2*)(r0 + d4);
            uint2 u1 = *(const uint2*)(r1 + d4);
            float2 a0 = bf2f(u0.x), a1 = bf2f(u0.y);
            float2 b0 = bf2f(u1.x), b1 = bf2f(u1.y);
            *(float4*)&Wsh[d4] = make_float4(a0.x+b0.x, a0.y+b0.y, a1.x+b1.x, a1.y+b1.y);
        }
        __syncthreads();
        float4 wp = *(const float4*)&Wsh[VV + i0];
        float v0 = Wsh[tsh[i0+0]] + wp.x;
        float v1 = Wsh[tsh[i0+1]] + wp.y;
        float v2 = Wsh[tsh[i0+2]] + wp.z;
        float v3 = Wsh[tsh[i0+3]] + wp.w;
        __nv_bfloat162 o0 = __floats2bfloat162_rn(v0, v1);
        __nv_bfloat162 o1 = __floats2bfloat162_rn(v2, v3);
        uint2 out; out.x = *(uint32_t*)&o0; out.y = *(uint32_t*)&o1;
        *(uint2*)(S + ((size_t)b*NN + m)*NN + i0) = out;
    }
}

// ---------------------------------------------------------------------------
// Causal row softmax: register-resident, one read / one exp / one 8B write.
// ---------------------------------------------------------------------------
__global__ void __launch_bounds__(256)
softmax_causal(const bf16* __restrict__ S, bf16* __restrict__ A) {
    int b = blockIdx.y, n = blockIdx.x;
    __shared__ float rs[8];
    const bf16* srow = S + ((size_t)b*NN + n)*NN;
    bf16*       arow = A + ((size_t)b*NN + n)*NN;
    int t = threadIdx.x;
    int i0 = t*4;
    uint2 raw = *(const uint2*)(srow + i0);
    float2 f0 = bf2f(raw.x);
    float2 f1 = bf2f(raw.y);
    float v[4] = { (i0+0 <= n) ? f0.x : -1e30f, (i0+1 <= n) ? f0.y : -1e30f,
                   (i0+2 <= n) ? f1.x : -1e30f, (i0+3 <= n) ? f1.y : -1e30f };
    float mx = fmaxf(fmaxf(v[0], v[1]), fmaxf(v[2], v[3]));
    mx = blk_max(mx, rs, t);
    __syncthreads();
    float e[4];
    #pragma unroll
    for (int k = 0; k < 4; k++)
        e[k] = (i0+k <= n) ? __expf(v[k] - mx) : 0.f;
    float sum = blk_sum(e[0]+e[1]+e[2]+e[3], rs, t);
    float inv = 1.f / sum;
    __nv_bfloat162 o0 = __floats2bfloat162_rn(e[0]*inv, e[1]*inv);
    __nv_bfloat162 o1 = __floats2bfloat162_rn(e[2]*inv, e[3]*inv);
    uint2 out; out.x = *(uint32_t*)&o0; out.y = *(uint32_t*)&o1;
    *(uint2*)(arow + i0) = out;
}

// ---------------------------------------------------------------------------
// Batched 1024^3 bf16 GEMM: mma.sync m16n8k16, ldmatrix, 3-stage cp.async.
// (unchanged from round 8)
// ---------------------------------------------------------------------------
#define ASTG_H (128*40)
template<int MODE>
struct BC { static constexpr int STR = 136, STG = 32*136; };
template<> struct BC<1> { static constexpr int STR = 40, STG = 128*40; };

template<int MODE>
__global__ void __launch_bounds__(256)
gemm_bf16(const bf16* __restrict__ Ag, const bf16* __restrict__ Bg,
          bf16* __restrict__ Cg) {
    constexpr int BSTR = BC<MODE>::STR;
    constexpr int BSTG = BC<MODE>::STG;
    int bi = blockIdx.y, bj = blockIdx.x, b = blockIdx.z;
    if (MODE != 0 && bj > bi) return;
    const bf16* Ab = Ag + (size_t)b*NN*NN;
    const bf16* Bb = Bg + (size_t)b*NN*NN;
    bf16*       Cb = Cg + (size_t)b*NN*NN;
    int k0 = (MODE == 2) ? bj*128 : 0;
    int k1 = (MODE == 1) ? (bj+1)*128 : (bi+1)*128;

    extern __shared__ __align__(16) bf16 sm[];
    uint32_t smbase = (uint32_t)__cvta_generic_to_shared(sm);
    uint32_t AB = smbase;
    uint32_t BBs = smbase + 3*ASTG_H*2;

    int tid  = threadIdx.x;
    int wid  = tid >> 5, lane = tid & 31;
    int gid  = lane >> 2, tig = lane & 3;
    int g    = lane >> 3, rsel = lane & 7;
    int wm   = (wid & 3) * 32;
    int wn   = (wid >> 2) * 64;
    int row0 = bi*128, col0 = bj*128;

    float c[2][8][4] = {};

    auto load_stage = [&](int s, int kb) {
        uint32_t Ad = AB + (s*ASTG_H)*2;
        #pragma unroll
        for (int h = 0; h < 2; h++) {
            int chunk = tid + 256*h;
            int r = chunk >> 2, c8 = (chunk & 3) * 8;
            uint32_t dst = Ad + (r*40 + c8)*2;
            const bf16* src = &Ab[(size_t)(row0 + r)*NN + kb + c8];
            asm volatile("cp.async.ca.shared.global [%0], [%1], 16;\n" :: "r"(dst), "l"(src));
        }
        uint32_t Bd = BBs + (s*BSTG)*2;
        if (MODE == 1) {
            #pragma unroll
            for (int h = 0; h < 2; h++) {
                int chunk = tid + 256*h;
                int r = chunk >> 2, c8 = (chunk & 3) * 8;
                uint32_t dst = Bd + (r*BSTR + c8)*2;
                const bf16* src = &Bb[(size_t)(col0 + r)*NN + kb + c8];
                asm volatile("cp.async.ca.shared.global [%0], [%1], 16;\n" :: "r"(dst), "l"(src));
            }
        } else {
            #pragma unroll
            for (int h = 0; h < 2; h++) {
                int chunk = tid + 256*h;
                int r = chunk >> 4, c8 = (chunk & 15) * 8;
                uint32_t dst = Bd + (r*BSTR + c8)*2;
                const bf16* src = &Bb[(size_t)(kb + r)*NN + col0 + c8];
                asm volatile("cp.async.ca.shared.global [%0], [%1], 16;\n" :: "r"(dst), "l"(src));
            }
        }
    };

    auto compute = [&](int s) {
        uint32_t Ac = AB + (s*ASTG_H)*2;
        uint32_t Bc = BBs + (s*BSTG)*2;
        #pragma unroll
        for (int kk = 0; kk < 32; kk += 16) {
            uint32_t a[2][4];
            #pragma unroll
            for (int i = 0; i < 2; i++) {
                int row = wm + i*16 + (g & 1)*8 + rsel;
                int col = kk + (g >> 1)*8;
                uint32_t addr = Ac + (row*40 + col)*2;
                asm volatile("ldmatrix.sync.aligned.m8n8.x4.shared.b16 {%0,%1,%2,%3}, [%4];"
                             : "=r"(a[i][0]), "=r"(a[i][1]), "=r"(a[i][2]), "=r"(a[i][3])
                             : "r"(addr));
            }
            uint32_t bfr[8][2];
            #pragma unroll
            for (int u = 0; u < 4; u++) {
                int n0 = wn + u*16;
                uint32_t r0, r1, r2, r3;
                if (MODE == 1) {
                    int n = n0 + (g >> 1)*8 + rsel;
                    int k = kk + (g & 1)*8;
                    uint32_t addr = Bc + (n*BSTR + k)*2;
                    asm volatile("ldmatrix.sync.aligned.m8n8.x4.shared.b16 {%0,%1,%2,%3}, [%4];"
                                 : "=r"(r0), "=r"(r1), "=r"(r2), "=r"(r3) : "r"(addr));
                } else {
                    int k = kk + (g & 1)*8 + rsel;
                    int n = n0 + (g >> 1)*8;
                    uint32_t addr = Bc + (k*BSTR + n)*2;
                    asm volatile("ldmatrix.sync.aligned.m8n8.x4.trans.shared.b16 {%0,%1,%2,%3}, [%4];"
                                 : "=r"(r0), "=r"(r1), "=r"(r2), "=r"(r3) : "r"(addr));
                }
                bfr[2*u  ][0] = r0; bfr[2*u  ][1] = r1;
                bfr[2*u+1][0] = r2; bfr[2*u+1][1] = r3;
            }
            #pragma unroll
            for (int i = 0; i < 2; i++)
                #pragma unroll
                for (int j = 0; j < 8; j++) {
                    asm volatile(
                        "mma.sync.aligned.m16n8k16.row.col.f32.bf16.bf16.f32 "
                        "{%0,%1,%2,%3}, {%4,%5,%6,%7}, {%8,%9}, {%0,%1,%2,%3};"
                        : "+f"(c[i][j][0]), "+f"(c[i][j][1]),
                          "+f"(c[i][j][2]), "+f"(c[i][j][3])
                        : "r"(a[i][0]), "r"(a[i][1]), "r"(a[i][2]), "r"(a[i][3]),
                          "r"(bfr[j][0]), "r"(bfr[j][1]));
                }
        }
    };

    int nslab = (k1 - k0) >> 5;
    load_stage(0, k0);
    asm volatile("cp.async.commit_group;\n");
    load_stage(1, k0 + 32);
    asm volatile("cp.async.commit_group;\n");

    int sc = 0, sl = 2;
    for (int t = 0; t < nslab - 1; t++) {
        asm volatile("cp.async.wait_group 1;\n");
        __syncthreads();
        if (t + 2 < nslab) {
            load_stage(sl, k0 + (t+2)*32);
            asm volatile("cp.async.commit_group;\n");
            sl = (sl == 2) ? 0 : sl + 1;
        }
        compute(sc);
        sc = (sc == 2) ? 0 : sc + 1;
    }
    asm volatile("cp.async.wait_group 0;\n");
    __syncthreads();
    compute(sc);

    #pragma unroll
    for (int i = 0; i < 2; i++) {
        #pragma unroll
        for (int j = 0; j < 8; j++) {
            int gc = col0 + wn + j*8 + tig*2;
            #pragma unroll
            for (int h = 0; h < 2; h++) {
                int gr = row0 + wm + i*16 + gid + h*8;
                float vx = c[i][j][h*2], vy = c[i][j][h*2+1];
                if (MODE == 2) {
                    if (gc+0 > gr) vx = 0.f;
                    if (gc+1 > gr) vy = 0.f;
                }
                __nv_bfloat162 v = __floats2bfloat162_rn(vx, vy);
                *(__nv_bfloat162*)&Cb[(size_t)gr*NN + gc] = v;
            }
        }
    }
}

// ---------------------------------------------------------------------------
// Layer 4 (row 1023 only) + logits
// q partials: block (bm, b) handles 32 m-values; 384 threads x 4 d each.
// ---------------------------------------------------------------------------
__global__ void __launch_bounds__(384)
l4_q_part(const bf16* __restrict__ Rb, const int* __restrict__ tok,
          const bf16* __restrict__ P, float* __restrict__ qp) {
    int b = blockIdx.y, bm = blockIdx.x;
    __shared__ float rsh[32];
    __shared__ int   tsh[32];
    int t = threadIdx.x;
    if (t < 32) {
        int m = bm*32 + t;
        rsh[t] = __bfloat162float(P[((size_t)b*NN + (NN-1))*NN + m]);
        tsh[t] = tok[b*NN + m];
    }
    __syncthreads();
    int d0 = t*4;
    float acc[4] = {};
    #pragma unroll 4
    for (int j = 0; j < 32; j++) {
        int m = bm*32 + j;
        float r = rsh[j];
        uint2 u0 = *(const uint2*)(Rb + (size_t)tsh[j]*DD + d0);
        uint2 u1 = *(const uint2*)(Rb + (size_t)(VV + m)*DD + d0);
        float2 a0 = bf2f(u0.x), a1 = bf2f(u0.y);
        float2 b0 = bf2f(u1.x), b1 = bf2f(u1.y);
        acc[0] += r * (a0.x + b0.x);
        acc[1] += r * (a0.y + b0.y);
        acc[2] += r * (a1.x + b1.x);
        acc[3] += r * (a1.y + b1.y);
    }
    *(float4*)&qp[((size_t)b*32 + bm)*DD + d0] = make_float4(acc[0], acc[1], acc[2], acc[3]);
}

// Reduce 32 partials -> q (smem), then u[m] = q[t_m] + q[V+m].
__global__ void __launch_bounds__(512)
l4_q_reduce(const float* __restrict__ qp, const int* __restrict__ tok,
            float* __restrict__ u) {
    int b = blockIdx.x;
    __shared__ float qsh[DD];
    int t = threadIdx.x;
    for (int d = t; d < DD; d += 512) {
        float acc = 0.f;
        #pragma unroll 8
        for (int bm = 0; bm < 32; bm++)
            acc += qp[((size_t)b*32 + bm)*DD + d];
        qsh[d] = acc;
    }
    __syncthreads();
    for (int m = t; m < NN; m += 512)
        u[b*NN + m] = qsh[tok[b*NN + m]] + qsh[VV + m];
}

__global__ void l4_srow(const float* __restrict__ u, const bf16* __restrict__ P,
                        float* __restrict__ srow) {
    int b = blockIdx.y;
    __shared__ float ush[NN];
    for (int i = threadIdx.x; i < NN; i += 256) ush[i] = u[b*NN + i];
    __syncthreads();
    int row  = blockIdx.x * 8 + (threadIdx.x >> 5);
    int lane = threadIdx.x & 31;
    const bf16* Prow = P + ((size_t)b*NN + row)*NN;
    float acc = 0.f;
    for (int k = lane; k < NN; k += 32) acc += ush[k] * __bfloat162float(Prow[k]);
    for (int o = 16; o; o >>= 1) acc += __shfl_down_sync(0xffffffffu, acc, o);
    if (lane == 0) srow[b*NN + row] = acc;
}

__global__ void l4_softmax(const float* __restrict__ s, float* __restrict__ a) {
    int b = blockIdx.x;
    __shared__ float rs[8];
    int t = threadIdx.x;
    int i0 = t*4;
    float4 v4 = *(const float4*)&s[b*NN + i0];
    float v[4] = { v4.x, v4.y, v4.z, v4.w };
    float mx = fmaxf(fmaxf(v[0], v[1]), fmaxf(v[2], v[3]));
    mx = blk_max(mx, rs, t);
    __syncthreads();
    float e[4];
    #pragma unroll
    for (int k = 0; k < 4; k++) e[k] = __expf(v[k] - mx);
    float sum = blk_sum(e[0]+e[1]+e[2]+e[3], rs, t);
    float inv = 1.f / sum;
    *(float4*)&a[b*NN + i0] = make_float4(e[0]*inv, e[1]*inv, e[2]*inv, e[3]*inv);
}

__global__ void l4_p(const float* __restrict__ a, const bf16* __restrict__ P,
                     float* __restrict__ p) {
    int b = blockIdx.y;
    int k = blockIdx.x * 256 + threadIdx.x;
    __shared__ float ash[NN];
    for (int i = threadIdx.x; i < NN; i += 256) ash[i] = a[b*NN + i];
    __syncthreads();
    float acc = 0.f;
    for (int m = 0; m < NN; m++) acc += ash[m] * __bfloat162float(P[((size_t)b*NN + m)*NN + k]);
    p[b*NN + k] = acc;
}

__global__ void l4_c(const int* __restrict__ tok, const float* __restrict__ p,
                     float* __restrict__ c) {
    int b = blockIdx.x;
    __shared__ float psh[NN];
    __shared__ int   tsh[NN];
    for (int i = threadIdx.x; i < NN; i += blockDim.x) {
        psh[i] = p[b*NN + i];
        tsh[i] = tok[b*NN + i];
    }
    __syncthreads();
    int w = threadIdx.x;  // blockDim.x == 512 == VV
    float acc = 0.f;
    for (int m = 0; m < NN; m++)
        if (tsh[m] == w) acc += psh[m];
    c[b*VV + w] = acc;
}

__global__ void l4_logits(const float* __restrict__ c, const float* __restrict__ p,
                          const float* __restrict__ U, float* __restrict__ out) {
    int b = blockIdx.y;
    __shared__ float hsh[DD];
    for (int i = threadIdx.x; i < VV; i += 256) hsh[i]      = c[b*VV + i];
    for (int i = threadIdx.x; i < NN; i += 256) hsh[VV + i] = p[b*NN + i];
    __syncthreads();
    int wid = threadIdx.x >> 5, lane = threadIdx.x & 31;
    int v = blockIdx.x * 8 + wid;
    const float* Ur = U + (size_t)v*DD;
    float acc = 0.f;
    for (int j = lane; j < DD; j += 32) acc += hsh[j] * Ur[j];
    for (int o = 16; o; o >>= 1) acc += __shfl_down_sync(0xffffffffu, acc, o);
    if (lane == 0) out[b*VV + v] = acc;
}

// ---------------------------------------------------------------------------
extern "C" void kernel_launch(void* const* d_in, const int* in_sizes, int n_in,
                              void* d_out, int out_size) {
    const int*   tok = (const int*)  d_in[0];
    const float* R   = (const float*)d_in[1];
    const float* U   = (const float*)d_in[2];
    float*       out = (float*)d_out;

    bf16 *Rb, *S, *P, *T, *A, *PN;
    float *qp, *u, *sr, *a, *p, *c;
    cudaGetSymbolAddress((void**)&Rb, g_Rb);
    cudaGetSymbolAddress((void**)&S,  g_S);
    cudaGetSymbolAddress((void**)&P,  g_P);
    cudaGetSymbolAddress((void**)&T,  g_T);
    cudaGetSymbolAddress((void**)&A,  g_A);
    cudaGetSymbolAddress((void**)&PN, g_PN);
    cudaGetSymbolAddress((void**)&qp, g_qp);
    cudaGetSymbolAddress((void**)&u,  g_u);
    cudaGetSymbolAddress((void**)&sr, g_sr);
    cudaGetSymbolAddress((void**)&a,  g_a);
    cudaGetSymbolAddress((void**)&p,  g_p);
    cudaGetSymbolAddress((void**)&c,  g_c);

    const int SM0 = (3*ASTG_H + 3*BC<0>::STG) * 2;
    const int SM1 = (3*ASTG_H + 3*BC<1>::STG) * 2;
    cudaFuncSetAttribute(gemm_bf16<0>, cudaFuncAttributeMaxDynamicSharedMemorySize, SM0);
    cudaFuncSetAttribute(gemm_bf16<1>, cudaFuncAttributeMaxDynamicSharedMemorySize, SM1);
    cudaFuncSetAttribute(gemm_bf16<2>, cudaFuncAttributeMaxDynamicSharedMemorySize, SM0);

    dim3 gRow(NN, BB), gRow4(NN/4, BB), gT(8, 8, BB);
    const size_t RS = (size_t)DD*DD;

    // R -> bf16 (all 4 layers): 4*DD*DD/1024 blocks
    r_to_bf16<<<(4*DD*DD)/1024, 256>>>(R, Rb);

    // Layer 1 fused: P2 = softmax(S1), bf16
    gather_softmax1<<<gRow, 256>>>(Rb + 0*RS, tok, P);

    // Layer 2: scores = P*S2*P^T ; A2 = softmax ; P3 = A2*P
    gather_S      <<<gRow4, 256>>>(Rb + 1*RS, tok, S);
    gemm_bf16<0>  <<<gT, 256, SM0>>>(P, S, T);
    gemm_bf16<1>  <<<gT, 256, SM1>>>(T, P, A);
    softmax_causal<<<gRow, 256>>>(A, A);
    gemm_bf16<2>  <<<gT, 256, SM0>>>(A, P, PN);

    // Layer 3: same with P3 (in PN) -> P4 (into P)
    gather_S      <<<gRow4, 256>>>(Rb + 2*RS, tok, S);
    gemm_bf16<0>  <<<gT, 256, SM0>>>(PN, S, T);
    gemm_bf16<1>  <<<gT, 256, SM1>>>(T, PN, A);
    softmax_causal<<<gRow, 256>>>(A, A);
    gemm_bf16<2>  <<<gT, 256, SM0>>>(A, PN, P);

    // Layer 4 (row 1023 only) + logits
    l4_q_part  <<<dim3(32, BB), 384>>>(Rb + 3*RS, tok, P, qp);
    l4_q_reduce<<<BB, 512>>>(qp, tok, u);
    l4_srow    <<<dim3(128, BB), 256>>>(u, P, sr);
    l4_softmax <<<BB, 256>>>(sr, a);
    l4_p       <<<dim3(4, BB), 256>>>(a, P, p);
    l4_c       <<<BB, 512>>>(tok, p, c);
    l4_logits  <<<dim3(64, BB), 256>>>(c, p, U, out);
}

// round 11
// speedup vs baseline: 5.4299x; 1.0994x over previous
#include <cuda_runtime.h>
#include <cuda_bf16.h>
#include <cstdint>

// Problem constants
#define BB 32
#define NN 1024
#define VV 512
#define DD 1536

typedef __nv_bfloat16 bf16;

// Scratch buffers (allocation-free rule: __device__ globals). Big tensors bf16.
__device__ bf16  g_Rb[(size_t)4*DD*DD];   // bf16 copy of R (all layers)
__device__ bf16  g_S [(size_t)BB*NN*NN];
__device__ bf16  g_P [(size_t)BB*NN*NN];
__device__ bf16  g_T [(size_t)BB*NN*NN];
__device__ bf16  g_A [(size_t)BB*NN*NN];
__device__ bf16  g_PN[(size_t)BB*NN*NN];
__device__ float g_qp[(size_t)BB*32*DD];
__device__ float g_u [BB*NN];
__device__ float g_sr[BB*NN];
__device__ float g_a [BB*NN];
__device__ float g_p [BB*NN];
__device__ float g_c [BB*VV];

__device__ __forceinline__ float2 bf2f(uint32_t u) {
    return __bfloat1622float2(*(__nv_bfloat162*)&u);
}

// Block-wide reductions over 8 warps (256 threads), value broadcast to all.
__device__ __forceinline__ float blk_max(float v, float* rs, int t) {
    #pragma unroll
    for (int o = 16; o; o >>= 1) v = fmaxf(v, __shfl_xor_sync(0xffffffffu, v, o));
    if ((t & 31) == 0) rs[t >> 5] = v;
    __syncthreads();
    float r = rs[0];
    #pragma unroll
    for (int w = 1; w < 8; w++) r = fmaxf(r, rs[w]);
    return r;
}
__device__ __forceinline__ float blk_sum(float v, float* rs, int t) {
    #pragma unroll
    for (int o = 16; o; o >>= 1) v += __shfl_xor_sync(0xffffffffu, v, o);
    if ((t & 31) == 0) rs[t >> 5] = v;
    __syncthreads();
    float r = rs[0];
    #pragma unroll
    for (int w = 1; w < 8; w++) r += rs[w];
    return r;
}

// ---------------------------------------------------------------------------
// R -> bf16 conversion
// ---------------------------------------------------------------------------
__global__ void r_to_bf16(const float* __restrict__ R, bf16* __restrict__ Rb) {
    size_t i = ((size_t)blockIdx.x * 256 + threadIdx.x) * 4;
    float4 v = *(const float4*)(R + i);
    __nv_bfloat162 o0 = __floats2bfloat162_rn(v.x, v.y);
    __nv_bfloat162 o1 = __floats2bfloat162_rn(v.z, v.w);
    uint2 out; out.x = *(uint32_t*)&o0; out.y = *(uint32_t*)&o1;
    *(uint2*)(Rb + i) = out;
}

// ---------------------------------------------------------------------------
// Fused layer 1: scores gathered from Wsh (bf16 R), register softmax.
// ---------------------------------------------------------------------------
__global__ void __launch_bounds__(256)
gather_softmax1(const bf16* __restrict__ Rb, const int* __restrict__ tok,
                bf16* __restrict__ P) {
    int b = blockIdx.y, m = blockIdx.x;
    __shared__ float Wsh[DD];
    __shared__ int   tsh[NN];
    __shared__ float rs[8];
    const int* tb = tok + b*NN;
    int t = threadIdx.x;
    int tm = tb[m];
    const bf16* r0 = Rb + (size_t)tm*DD;
    const bf16* r1 = Rb + (size_t)(VV + m)*DD;
    for (int d4 = t*4; d4 < DD; d4 += 1024) {
        uint2 u0 = *(const uint2*)(r0 + d4);
        uint2 u1 = *(const uint2*)(r1 + d4);
        float2 a0 = bf2f(u0.x), a1 = bf2f(u0.y);
        float2 b0 = bf2f(u1.x), b1 = bf2f(u1.y);
        *(float4*)&Wsh[d4] = make_float4(a0.x+b0.x, a0.y+b0.y, a1.x+b1.x, a1.y+b1.y);
    }
    for (int i = t; i < NN; i += 256) tsh[i] = tb[i];
    __syncthreads();

    int i0 = t*4;
    float v[4];
    #pragma unroll
    for (int k = 0; k < 4; k++)
        v[k] = (i0+k <= m) ? (Wsh[tsh[i0+k]] + Wsh[VV + i0+k]) : -1e30f;
    float mx = fmaxf(fmaxf(v[0], v[1]), fmaxf(v[2], v[3]));
    mx = blk_max(mx, rs, t);
    __syncthreads();
    float e[4];
    #pragma unroll
    for (int k = 0; k < 4; k++)
        e[k] = (i0+k <= m) ? __expf(v[k] - mx) : 0.f;
    float sum = blk_sum(e[0]+e[1]+e[2]+e[3], rs, t);
    float inv = 1.f / sum;
    bf16* arow = P + ((size_t)b*NN + m)*NN;
    __nv_bfloat162 o0 = __floats2bfloat162_rn(e[0]*inv, e[1]*inv);
    __nv_bfloat162 o1 = __floats2bfloat162_rn(e[2]*inv, e[3]*inv);
    uint2 out; out.x = *(uint32_t*)&o0; out.y = *(uint32_t*)&o1;
    *(uint2*)(arow + i0) = out;
}

// ---------------------------------------------------------------------------
// S_k gather (bf16 R): 4 rows per block, 8B vector loads/stores.
// ---------------------------------------------------------------------------
__global__ void __launch_bounds__(256)
gather_S(const bf16* __restrict__ Rb, const int* __restrict__ tok,
         bf16* __restrict__ S) {
    int b = blockIdx.y;
    __shared__ float Wsh[DD];
    __shared__ int   tsh[NN];
    const int* tb = tok + b*NN;
    int t = threadIdx.x;
    for (int i = t; i < NN; i += 256) tsh[i] = tb[i];
    int i0 = t*4;
    #pragma unroll
    for (int r = 0; r < 4; r++) {
        int m = blockIdx.x*4 + r;
        __syncthreads();
        int tm = tb[m];
        const bf16* r0 = Rb + (size_t)tm*DD;
        const bf16* r1 = Rb + (size_t)(VV + m)*DD;
        for (int d4 = t*4; d4 < DD; d4 += 1024) {
            uint2 u0 = *(const uint2*)(r0 + d4);
            uint2 u1 = *(const uint2*)(r1 + d4);
            float2 a0 = bf2f(u0.x), a1 = bf2f(u0.y);
            float2 b0 = bf2f(u1.x), b1 = bf2f(u1.y);
            *(float4*)&Wsh[d4] = make_float4(a0.x+b0.x, a0.y+b0.y, a1.x+b1.x, a1.y+b1.y);
        }
        __syncthreads();
        float4 wp = *(const float4*)&Wsh[VV + i0];
        float v0 = Wsh[tsh[i0+0]] + wp.x;
        float v1 = Wsh[tsh[i0+1]] + wp.y;
        float v2 = Wsh[tsh[i0+2]] + wp.z;
        float v3 = Wsh[tsh[i0+3]] + wp.w;
        __nv_bfloat162 o0 = __floats2bfloat162_rn(v0, v1);
        __nv_bfloat162 o1 = __floats2bfloat162_rn(v2, v3);
        uint2 out; out.x = *(uint32_t*)&o0; out.y = *(uint32_t*)&o1;
        *(uint2*)(S + ((size_t)b*NN + m)*NN + i0) = out;
    }
}

// ---------------------------------------------------------------------------
// Causal row softmax: register-resident; loads predicated past the boundary.
// ---------------------------------------------------------------------------
__global__ void __launch_bounds__(256)
softmax_causal(const bf16* __restrict__ S, bf16* __restrict__ A) {
    int b = blockIdx.y, n = blockIdx.x;
    __shared__ float rs[8];
    const bf16* srow = S + ((size_t)b*NN + n)*NN;
    bf16*       arow = A + ((size_t)b*NN + n)*NN;
    int t = threadIdx.x;
    int i0 = t*4;
    float v[4] = { -1e30f, -1e30f, -1e30f, -1e30f };
    if (i0 <= n) {                 // skip loads wholly past the causal boundary
        uint2 raw = *(const uint2*)(srow + i0);
        float2 f0 = bf2f(raw.x);
        float2 f1 = bf2f(raw.y);
        v[0] = f0.x;
        if (i0+1 <= n) v[1] = f0.y;
        if (i0+2 <= n) v[2] = f1.x;
        if (i0+3 <= n) v[3] = f1.y;
    }
    float mx = fmaxf(fmaxf(v[0], v[1]), fmaxf(v[2], v[3]));
    mx = blk_max(mx, rs, t);
    __syncthreads();
    float e[4];
    #pragma unroll
    for (int k = 0; k < 4; k++)
        e[k] = (i0+k <= n) ? __expf(v[k] - mx) : 0.f;
    float sum = blk_sum(e[0]+e[1]+e[2]+e[3], rs, t);
    float inv = 1.f / sum;
    __nv_bfloat162 o0 = __floats2bfloat162_rn(e[0]*inv, e[1]*inv);
    __nv_bfloat162 o1 = __floats2bfloat162_rn(e[2]*inv, e[3]*inv);
    uint2 out; out.x = *(uint32_t*)&o0; out.y = *(uint32_t*)&o1;
    *(uint2*)(arow + i0) = out;
}

// ---------------------------------------------------------------------------
// Batched bf16 GEMM: mma.sync m16n8k16, ldmatrix, 3-stage cp.async.
// ALL modes now triangular (bj <= bi):
// MODE 0: C = A*B      k in [0,(bi+1)*128)        (T upper tiles never read)
// MODE 1: C = A*B^T    k in [0,(bj+1)*128)
// MODE 2: C = A*B      k in [bj*128,(bi+1)*128),  zero strict-upper entries
// bi reversed (heavy row-tiles scheduled first).
// ---------------------------------------------------------------------------
#define ASTG_H (128*40)
template<int MODE>
struct BC { static constexpr int STR = 136, STG = 32*136; };
template<> struct BC<1> { static constexpr int STR = 40, STG = 128*40; };

template<int MODE>
__global__ void __launch_bounds__(256)
gemm_bf16(const bf16* __restrict__ Ag, const bf16* __restrict__ Bg,
          bf16* __restrict__ Cg) {
    constexpr int BSTR = BC<MODE>::STR;
    constexpr int BSTG = BC<MODE>::STG;
    int bi = (int)gridDim.y - 1 - (int)blockIdx.y;   // heavy tiles first
    int bj = blockIdx.x, b = blockIdx.z;
    if (bj > bi) return;                             // all modes triangular
    const bf16* Ab = Ag + (size_t)b*NN*NN;
    const bf16* Bb = Bg + (size_t)b*NN*NN;
    bf16*       Cb = Cg + (size_t)b*NN*NN;
    int k0 = (MODE == 2) ? bj*128 : 0;
    int k1 = (MODE == 1) ? (bj+1)*128 : (bi+1)*128;

    extern __shared__ __align__(16) bf16 sm[];
    uint32_t smbase = (uint32_t)__cvta_generic_to_shared(sm);
    uint32_t AB = smbase;
    uint32_t BBs = smbase + 3*ASTG_H*2;

    int tid  = threadIdx.x;
    int wid  = tid >> 5, lane = tid & 31;
    int gid  = lane >> 2, tig = lane & 3;
    int g    = lane >> 3, rsel = lane & 7;
    int wm   = (wid & 3) * 32;
    int wn   = (wid >> 2) * 64;
    int row0 = bi*128, col0 = bj*128;

    float c[2][8][4] = {};

    auto load_stage = [&](int s, int kb) {
        uint32_t Ad = AB + (s*ASTG_H)*2;
        #pragma unroll
        for (int h = 0; h < 2; h++) {
            int chunk = tid + 256*h;
            int r = chunk >> 2, c8 = (chunk & 3) * 8;
            uint32_t dst = Ad + (r*40 + c8)*2;
            const bf16* src = &Ab[(size_t)(row0 + r)*NN + kb + c8];
            asm volatile("cp.async.ca.shared.global [%0], [%1], 16;\n" :: "r"(dst), "l"(src));
        }
        uint32_t Bd = BBs + (s*BSTG)*2;
        if (MODE == 1) {
            #pragma unroll
            for (int h = 0; h < 2; h++) {
                int chunk = tid + 256*h;
                int r = chunk >> 2, c8 = (chunk & 3) * 8;
                uint32_t dst = Bd + (r*BSTR + c8)*2;
                const bf16* src = &Bb[(size_t)(col0 + r)*NN + kb + c8];
                asm volatile("cp.async.ca.shared.global [%0], [%1], 16;\n" :: "r"(dst), "l"(src));
            }
        } else {
            #pragma unroll
            for (int h = 0; h < 2; h++) {
                int chunk = tid + 256*h;
                int r = chunk >> 4, c8 = (chunk & 15) * 8;
                uint32_t dst = Bd + (r*BSTR + c8)*2;
                const bf16* src = &Bb[(size_t)(kb + r)*NN + col0 + c8];
                asm volatile("cp.async.ca.shared.global [%0], [%1], 16;\n" :: "r"(dst), "l"(src));
            }
        }
    };

    auto compute = [&](int s) {
        uint32_t Ac = AB + (s*ASTG_H)*2;
        uint32_t Bc = BBs + (s*BSTG)*2;
        #pragma unroll
        for (int kk = 0; kk < 32; kk += 16) {
            uint32_t a[2][4];
            #pragma unroll
            for (int i = 0; i < 2; i++) {
                int row = wm + i*16 + (g & 1)*8 + rsel;
                int col = kk + (g >> 1)*8;
                uint32_t addr = Ac + (row*40 + col)*2;
                asm volatile("ldmatrix.sync.aligned.m8n8.x4.shared.b16 {%0,%1,%2,%3}, [%4];"
                             : "=r"(a[i][0]), "=r"(a[i][1]), "=r"(a[i][2]), "=r"(a[i][3])
                             : "r"(addr));
            }
            uint32_t bfr[8][2];
            #pragma unroll
            for (int u = 0; u < 4; u++) {
                int n0 = wn + u*16;
                uint32_t r0, r1, r2, r3;
                if (MODE == 1) {
                    int n = n0 + (g >> 1)*8 + rsel;
                    int k = kk + (g & 1)*8;
                    uint32_t addr = Bc + (n*BSTR + k)*2;
                    asm volatile("ldmatrix.sync.aligned.m8n8.x4.shared.b16 {%0,%1,%2,%3}, [%4];"
                                 : "=r"(r0), "=r"(r1), "=r"(r2), "=r"(r3) : "r"(addr));
                } else {
                    int k = kk + (g & 1)*8 + rsel;
                    int n = n0 + (g >> 1)*8;
                    uint32_t addr = Bc + (k*BSTR + n)*2;
                    asm volatile("ldmatrix.sync.aligned.m8n8.x4.trans.shared.b16 {%0,%1,%2,%3}, [%4];"
                                 : "=r"(r0), "=r"(r1), "=r"(r2), "=r"(r3) : "r"(addr));
                }
                bfr[2*u  ][0] = r0; bfr[2*u  ][1] = r1;
                bfr[2*u+1][0] = r2; bfr[2*u+1][1] = r3;
            }
            #pragma unroll
            for (int i = 0; i < 2; i++)
                #pragma unroll
                for (int j = 0; j < 8; j++) {
                    asm volatile(
                        "mma.sync.aligned.m16n8k16.row.col.f32.bf16.bf16.f32 "
                        "{%0,%1,%2,%3}, {%4,%5,%6,%7}, {%8,%9}, {%0,%1,%2,%3};"
                        : "+f"(c[i][j][0]), "+f"(c[i][j][1]),
                          "+f"(c[i][j][2]), "+f"(c[i][j][3])
                        : "r"(a[i][0]), "r"(a[i][1]), "r"(a[i][2]), "r"(a[i][3]),
                          "r"(bfr[j][0]), "r"(bfr[j][1]));
                }
        }
    };

    int nslab = (k1 - k0) >> 5;
    load_stage(0, k0);
    asm volatile("cp.async.commit_group;\n");
    load_stage(1, k0 + 32);
    asm volatile("cp.async.commit_group;\n");

    int sc = 0, sl = 2;
    for (int t = 0; t < nslab - 1; t++) {
        asm volatile("cp.async.wait_group 1;\n");
        __syncthreads();
        if (t + 2 < nslab) {
            load_stage(sl, k0 + (t+2)*32);
            asm volatile("cp.async.commit_group;\n");
            sl = (sl == 2) ? 0 : sl + 1;
        }
        compute(sc);
        sc = (sc == 2) ? 0 : sc + 1;
    }
    asm volatile("cp.async.wait_group 0;\n");
    __syncthreads();
    compute(sc);

    #pragma unroll
    for (int i = 0; i < 2; i++) {
        #pragma unroll
        for (int j = 0; j < 8; j++) {
            int gc = col0 + wn + j*8 + tig*2;
            #pragma unroll
            for (int h = 0; h < 2; h++) {
                int gr = row0 + wm + i*16 + gid + h*8;
                float vx = c[i][j][h*2], vy = c[i][j][h*2+1];
                if (MODE == 2) {
                    if (gc+0 > gr) vx = 0.f;
                    if (gc+1 > gr) vy = 0.f;
                }
                __nv_bfloat162 v = __floats2bfloat162_rn(vx, vy);
                *(__nv_bfloat162*)&Cb[(size_t)gr*NN + gc] = v;
            }
        }
    }
}

// ---------------------------------------------------------------------------
// Layer 4 (row 1023 only) + logits
// ---------------------------------------------------------------------------
__global__ void __launch_bounds__(384)
l4_q_part(const bf16* __restrict__ Rb, const int* __restrict__ tok,
          const bf16* __restrict__ P, float* __restrict__ qp) {
    int b = blockIdx.y, bm = blockIdx.x;
    __shared__ float rsh[32];
    __shared__ int   tsh[32];
    int t = threadIdx.x;
    if (t < 32) {
        int m = bm*32 + t;
        rsh[t] = __bfloat162float(P[((size_t)b*NN + (NN-1))*NN + m]);
        tsh[t] = tok[b*NN + m];
    }
    __syncthreads();
    int d0 = t*4;
    float acc[4] = {};
    #pragma unroll 4
    for (int j = 0; j < 32; j++) {
        int m = bm*32 + j;
        float r = rsh[j];
        uint2 u0 = *(const uint2*)(Rb + (size_t)tsh[j]*DD + d0);
        uint2 u1 = *(const uint2*)(Rb + (size_t)(VV + m)*DD + d0);
        float2 a0 = bf2f(u0.x), a1 = bf2f(u0.y);
        float2 b0 = bf2f(u1.x), b1 = bf2f(u1.y);
        acc[0] += r * (a0.x + b0.x);
        acc[1] += r * (a0.y + b0.y);
        acc[2] += r * (a1.x + b1.x);
        acc[3] += r * (a1.y + b1.y);
    }
    *(float4*)&qp[((size_t)b*32 + bm)*DD + d0] = make_float4(acc[0], acc[1], acc[2], acc[3]);
}

__global__ void __launch_bounds__(512)
l4_q_reduce(const float* __restrict__ qp, const int* __restrict__ tok,
            float* __restrict__ u) {
    int b = blockIdx.x;
    __shared__ float qsh[DD];
    int t = threadIdx.x;
    for (int d = t; d < DD; d += 512) {
        float acc = 0.f;
        #pragma unroll 8
        for (int bm = 0; bm < 32; bm++)
            acc += qp[((size_t)b*32 + bm)*DD + d];
        qsh[d] = acc;
    }
    __syncthreads();
    for (int m = t; m < NN; m += 512)
        u[b*NN + m] = qsh[tok[b*NN + m]] + qsh[VV + m];
}

__global__ void l4_srow(const float* __restrict__ u, const bf16* __restrict__ P,
                        float* __restrict__ srow) {
    int b = blockIdx.y;
    __shared__ float ush[NN];
    for (int i = threadIdx.x; i < NN; i += 256) ush[i] = u[b*NN + i];
    __syncthreads();
    int row  = blockIdx.x * 8 + (threadIdx.x >> 5);
    int lane = threadIdx.x & 31;
    const bf16* Prow = P + ((size_t)b*NN + row)*NN;
    float acc = 0.f;
    for (int k = lane; k < NN; k += 32) acc += ush[k] * __bfloat162float(Prow[k]);
    for (int o = 16; o; o >>= 1) acc += __shfl_down_sync(0xffffffffu, acc, o);
    if (lane == 0) srow[b*NN + row] = acc;
}

__global__ void l4_softmax(const float* __restrict__ s, float* __restrict__ a) {
    int b = blockIdx.x;
    __shared__ float rs[8];
    int t = threadIdx.x;
    int i0 = t*4;
    float4 v4 = *(const float4*)&s[b*NN + i0];
    float v[4] = { v4.x, v4.y, v4.z, v4.w };
    float mx = fmaxf(fmaxf(v[0], v[1]), fmaxf(v[2], v[3]));
    mx = blk_max(mx, rs, t);
    __syncthreads();
    float e[4];
    #pragma unroll
    for (int k = 0; k < 4; k++) e[k] = __expf(v[k] - mx);
    float sum = blk_sum(e[0]+e[1]+e[2]+e[3], rs, t);
    float inv = 1.f / sum;
    *(float4*)&a[b*NN + i0] = make_float4(e[0]*inv, e[1]*inv, e[2]*inv, e[3]*inv);
}

__global__ void l4_p(const float* __restrict__ a, const bf16* __restrict__ P,
                     float* __restrict__ p) {
    int b = blockIdx.y;
    int k = blockIdx.x * 256 + threadIdx.x;
    __shared__ float ash[NN];
    for (int i = threadIdx.x; i < NN; i += 256) ash[i] = a[b*NN + i];
    __syncthreads();
    float acc = 0.f;
    for (int m = 0; m < NN; m++) acc += ash[m] * __bfloat162float(P[((size_t)b*NN + m)*NN + k]);
    p[b*NN + k] = acc;
}

__global__ void l4_c(const int* __restrict__ tok, const float* __restrict__ p,
                     float* __restrict__ c) {
    int b = blockIdx.x;
    __shared__ float psh[NN];
    __shared__ int   tsh[NN];
    for (int i = threadIdx.x; i < NN; i += blockDim.x) {
        psh[i] = p[b*NN + i];
        tsh[i] = tok[b*NN + i];
    }
    __syncthreads();
    int w = threadIdx.x;  // blockDim.x == 512 == VV
    float acc = 0.f;
    for (int m = 0; m < NN; m++)
        if (tsh[m] == w) acc += psh[m];
    c[b*VV + w] = acc;
}

__global__ void l4_logits(const float* __restrict__ c, const float* __restrict__ p,
                          const float* __restrict__ U, float* __restrict__ out) {
    int b = blockIdx.y;
    __shared__ float hsh[DD];
    for (int i = threadIdx.x; i < VV; i += 256) hsh[i]      = c[b*VV + i];
    for (int i = threadIdx.x; i < NN; i += 256) hsh[VV + i] = p[b*NN + i];
    __syncthreads();
    int wid = threadIdx.x >> 5, lane = threadIdx.x & 31;
    int v = blockIdx.x * 8 + wid;
    const float* Ur = U + (size_t)v*DD;
    float acc = 0.f;
    for (int j = lane; j < DD; j += 32) acc += hsh[j] * Ur[j];
    for (int o = 16; o; o >>= 1) acc += __shfl_down_sync(0xffffffffu, acc, o);
    if (lane == 0) out[b*VV + v] = acc;
}

// ---------------------------------------------------------------------------
extern "C" void kernel_launch(void* const* d_in, const int* in_sizes, int n_in,
                              void* d_out, int out_size) {
    const int*   tok = (const int*)  d_in[0];
    const float* R   = (const float*)d_in[1];
    const float* U   = (const float*)d_in[2];
    float*       out = (float*)d_out;

    bf16 *Rb, *S, *P, *T, *A, *PN;
    float *qp, *u, *sr, *a, *p, *c;
    cudaGetSymbolAddress((void**)&Rb, g_Rb);
    cudaGetSymbolAddress((void**)&S,  g_S);
    cudaGetSymbolAddress((void**)&P,  g_P);
    cudaGetSymbolAddress((void**)&T,  g_T);
    cudaGetSymbolAddress((void**)&A,  g_A);
    cudaGetSymbolAddress((void**)&PN, g_PN);
    cudaGetSymbolAddress((void**)&qp, g_qp);
    cudaGetSymbolAddress((void**)&u,  g_u);
    cudaGetSymbolAddress((void**)&sr, g_sr);
    cudaGetSymbolAddress((void**)&a,  g_a);
    cudaGetSymbolAddress((void**)&p,  g_p);
    cudaGetSymbolAddress((void**)&c,  g_c);

    const int SM0 = (3*ASTG_H + 3*BC<0>::STG) * 2;
    const int SM1 = (3*ASTG_H + 3*BC<1>::STG) * 2;
    cudaFuncSetAttribute(gemm_bf16<0>, cudaFuncAttributeMaxDynamicSharedMemorySize, SM0);
    cudaFuncSetAttribute(gemm_bf16<1>, cudaFuncAttributeMaxDynamicSharedMemorySize, SM1);
    cudaFuncSetAttribute(gemm_bf16<2>, cudaFuncAttributeMaxDynamicSharedMemorySize, SM0);

    dim3 gRow(NN, BB), gRow4(NN/4, BB), gT(8, 8, BB);
    const size_t RS = (size_t)DD*DD;

    r_to_bf16<<<(4*DD*DD)/1024, 256>>>(R, Rb);

    // Layer 1 fused: P2 = softmax(S1), bf16
    gather_softmax1<<<gRow, 256>>>(Rb + 0*RS, tok, P);

    // Layer 2: scores = P*S2*P^T ; A2 = softmax ; P3 = A2*P
    gather_S      <<<gRow4, 256>>>(Rb + 1*RS, tok, S);
    gemm_bf16<0>  <<<gT, 256, SM0>>>(P, S, T);
    gemm_bf16<1>  <<<gT, 256, SM1>>>(T, P, A);
    softmax_causal<<<gRow, 256>>>(A, A);
    gemm_bf16<2>  <<<gT, 256, SM0>>>(A, P, PN);

    // Layer 3: same with P3 (in PN) -> P4 (into P)
    gather_S      <<<gRow4, 256>>>(Rb + 2*RS, tok, S);
    gemm_bf16<0>  <<<gT, 256, SM0>>>(PN, S, T);
    gemm_bf16<1>  <<<gT, 256, SM1>>>(T, PN, A);
    softmax_causal<<<gRow, 256>>>(A, A);
    gemm_bf16<2>  <<<gT, 256, SM0>>>(A, PN, P);

    // Layer 4 (row 1023 only) + logits
    l4_q_part  <<<dim3(32, BB), 384>>>(Rb + 3*RS, tok, P, qp);
    l4_q_reduce<<<BB, 512>>>(qp, tok, u);
    l4_srow    <<<dim3(128, BB), 256>>>(u, P, sr);
    l4_softmax <<<BB, 256>>>(sr, a);
    l4_p       <<<dim3(4, BB), 256>>>(a, P, p);
    l4_c       <<<BB, 512>>>(tok, p, c);
    l4_logits  <<<dim3(64, BB), 256>>>(c, p, U, out);
}